// round 4
// baseline (speedup 1.0000x reference)
#include <cuda_runtime.h>
#include <math.h>

#define NMAX 100000
#define EMAX 1600000
#define FULL 0xffffffffu

// ---------------- scratch (static device globals; no allocations) ----------
__device__ int   g_count[NMAX];
__device__ int   g_rowstart[NMAX + 1];
__device__ int   g_cursor[NMAX];
__device__ int   g_srcs[EMAX];
__device__ float g_invdeg[NMAX];
__device__ int   g_bsum[64];
__device__ int   g_bbase[64];
__device__ float g_u[NMAX * 128];    // x @ Wl1
__device__ float g_v[NMAX * 128];    // x @ Wr1 + b1
__device__ float g_h[NMAX * 128];    // hidden features
__device__ float g_z[NMAX * 64];     // h @ Wl2
__device__ float g_pre[NMAX * 64];   // h @ Wr2 + b2

// ---------------- f32x2 helpers (packed fp32 SIMD FMA) ---------------------
__device__ __forceinline__ unsigned long long bcast2(float a) {
    unsigned long long d;
    unsigned int r = __float_as_uint(a);
    asm("mov.b64 %0, {%1, %1};" : "=l"(d) : "r"(r));
    return d;
}
__device__ __forceinline__ unsigned long long fma2(unsigned long long a,
                                                   unsigned long long b,
                                                   unsigned long long c) {
    unsigned long long d;
    asm("fma.rn.f32x2 %0, %1, %2, %3;" : "=l"(d) : "l"(a), "l"(b), "l"(c));
    return d;
}
__device__ __forceinline__ float2 unpack2(unsigned long long v) {
    unsigned int lo, hi;
    asm("mov.b64 {%0, %1}, %2;" : "=r"(lo), "=r"(hi) : "l"(v));
    return make_float2(__uint_as_float(lo), __uint_as_float(hi));
}

// ---------------- CSR build -------------------------------------------------
__global__ void k_zero(int n) {
    int i = blockIdx.x * blockDim.x + threadIdx.x;
    if (i < n) g_count[i] = 0;
}

__global__ void k_hist(const int* __restrict__ dst, int e) {
    int i = blockIdx.x * blockDim.x + threadIdx.x;
    if (i < e) atomicAdd(&g_count[dst[i]], 1);
}

__global__ void k_bsum(int n) {
    const int tid = threadIdx.x;
    const int gbase = blockIdx.x * 2048 + tid * 4;
    int s = 0;
#pragma unroll
    for (int j = 0; j < 4; j++)
        if (gbase + j < n) s += g_count[gbase + j];
    const int lane = tid & 31, wid = tid >> 5;
#pragma unroll
    for (int off = 16; off > 0; off >>= 1) s += __shfl_down_sync(FULL, s, off);
    __shared__ int w[16];
    if (lane == 0) w[wid] = s;
    __syncthreads();
    if (tid == 0) {
        int t = 0;
#pragma unroll
        for (int i = 0; i < 16; i++) t += w[i];
        g_bsum[blockIdx.x] = t;
    }
}

__global__ void k_bscan(int B, int n, int e) {
    __shared__ int s[64];
    const int t = threadIdx.x;
    int v = (t < B) ? g_bsum[t] : 0;
    s[t] = v;
    __syncthreads();
    for (int off = 1; off < 64; off <<= 1) {
        int u = (t >= off) ? s[t - off] : 0;
        __syncthreads();
        s[t] += u;
        __syncthreads();
    }
    if (t < B) g_bbase[t] = s[t] - v;
    if (t == 0) g_rowstart[n] = e;
}

__global__ void k_fill(int n) {
    const int tid = threadIdx.x;
    const int lane = tid & 31, wid = tid >> 5;
    const int gbase = blockIdx.x * 2048 + tid * 4;
    int c[4];
    int s = 0;
#pragma unroll
    for (int j = 0; j < 4; j++) {
        c[j] = (gbase + j < n) ? g_count[gbase + j] : 0;
        s += c[j];
    }
    int incl = s;
#pragma unroll
    for (int off = 1; off < 32; off <<= 1) {
        int u = __shfl_up_sync(FULL, incl, off);
        if (lane >= off) incl += u;
    }
    __shared__ int wsum[16];
    if (lane == 31) wsum[wid] = incl;
    __syncthreads();
    if (tid < 16) {
        int v = wsum[tid];
#pragma unroll
        for (int off = 1; off < 16; off <<= 1) {
            int u = __shfl_up_sync(0xffffu, v, off);
            if (tid >= off) v += u;
        }
        wsum[tid] = v;
    }
    __syncthreads();
    int base = g_bbase[blockIdx.x] + (incl - s) + (wid ? wsum[wid - 1] : 0);
#pragma unroll
    for (int j = 0; j < 4; j++) {
        if (gbase + j < n) {
            g_rowstart[gbase + j] = base;
            g_cursor[gbase + j] = base;
            g_invdeg[gbase + j] = 1.0f / fmaxf((float)c[j], 1.0f);
            base += c[j];
        }
    }
}

__global__ void k_scatter(const int* __restrict__ src, const int* __restrict__ dst, int e) {
    int i = blockIdx.x * blockDim.x + threadIdx.x;
    if (i < e) {
        int pos = atomicAdd(&g_cursor[dst[i]], 1);
        g_srcs[pos] = src[i];
    }
}

// ---------------- x projections: u = x@Wl1, v = x@Wr1 + b1 ------------------
// 256 threads; tile 128 rows; A staged once, W swapped per half.
#define G_SMEM ((128 * 128 + 128 * 132) * 4)
__global__ __launch_bounds__(256, 1)
void k_xproj(const float* __restrict__ x,
             const float* __restrict__ Wl, const float* __restrict__ Wr,
             const float* __restrict__ bias,
             float* __restrict__ u, float* __restrict__ v, int n)
{
    extern __shared__ float sm[];
    float* sW = sm;                // [128][128]
    float* sA = sm + 128 * 128;    // [128][132]
    const int tid = threadIdx.x;
    const int row0 = blockIdx.x * 128;
    const int tx = tid & 15, ty = tid >> 4;

    const float4* x4 = (const float4*)x;
    for (int i = tid; i < 4096; i += 256) {
        int r = i >> 5, q = i & 31;
        int gr = row0 + r;
        float4 vv = make_float4(0.f, 0.f, 0.f, 0.f);
        if (gr < n) vv = __ldg(&x4[gr * 32 + q]);
        *(float4*)&sA[r * 132 + q * 4] = vv;
    }

    float4* sW4 = (float4*)sW;
    const float4* b4 = (const float4*)bias;
    const float4 bv0 = __ldg(&b4[tx]);
    const float4 bv1 = __ldg(&b4[16 + tx]);

#pragma unroll 1
    for (int half = 0; half < 2; half++) {
        const float4* Wsrc = (const float4*)(half ? Wr : Wl);
        for (int i = tid; i < 4096; i += 256) sW4[i] = __ldg(&Wsrc[i]);
        __syncthreads();

        unsigned long long acc[8][4];
#pragma unroll
        for (int i = 0; i < 8; i++)
#pragma unroll
            for (int j = 0; j < 4; j++) acc[i][j] = 0ull;

        const ulonglong2* sW2 = (const ulonglong2*)sW;
        const float* sa = &sA[ty * 8 * 132];
#pragma unroll 2
        for (int k = 0; k < 128; k++) {
            ulonglong2 wA = sW2[k * 32 + tx];
            ulonglong2 wB = sW2[k * 32 + 16 + tx];
#pragma unroll
            for (int i = 0; i < 8; i++) {
                unsigned long long aa = bcast2(sa[i * 132 + k]);
                acc[i][0] = fma2(aa, wA.x, acc[i][0]);
                acc[i][1] = fma2(aa, wA.y, acc[i][1]);
                acc[i][2] = fma2(aa, wB.x, acc[i][2]);
                acc[i][3] = fma2(aa, wB.y, acc[i][3]);
            }
        }
        __syncthreads();   // all done reading sW before next half reloads it

        float4* outp = (float4*)(half ? v : u);
#pragma unroll
        for (int i = 0; i < 8; i++) {
            int gr = row0 + ty * 8 + i;
            if (gr >= n) break;
            float2 p0 = unpack2(acc[i][0]), p1 = unpack2(acc[i][1]);
            float2 p2 = unpack2(acc[i][2]), p3 = unpack2(acc[i][3]);
            float4 o0 = make_float4(p0.x, p0.y, p1.x, p1.y);
            float4 o1 = make_float4(p2.x, p2.y, p3.x, p3.y);
            if (half) {
                o0.x += bv0.x; o0.y += bv0.y; o0.z += bv0.z; o0.w += bv0.w;
                o1.x += bv1.x; o1.y += bv1.y; o1.z += bv1.z; o1.w += bv1.w;
            }
            outp[gr * 32 + tx]      = o0;
            outp[gr * 32 + 16 + tx] = o1;
        }
    }
}

// ---------------- fused: h = relu(mean_agg(u) + v) --------------------------
__global__ void k_aggrelu(const float4* __restrict__ u, const float4* __restrict__ v,
                          float4* __restrict__ h, int n)
{
    int node = blockIdx.x * (blockDim.x >> 5) + (threadIdx.x >> 5);
    if (node >= n) return;
    const int lane = threadIdx.x & 31;
    const int beg = g_rowstart[node];
    const int cnt = g_rowstart[node + 1] - beg;

    float4 a0 = make_float4(0.f, 0.f, 0.f, 0.f);
    float4 a1 = make_float4(0.f, 0.f, 0.f, 0.f);
    float4 a2 = make_float4(0.f, 0.f, 0.f, 0.f);
    float4 a3 = make_float4(0.f, 0.f, 0.f, 0.f);

    for (int base = 0; base < cnt; base += 32) {
        const int m = min(32, cnt - base);
        int idx = (lane < m) ? __ldg(&g_srcs[beg + base + lane]) : 0;
        int j = 0;
        for (; j + 3 < m; j += 4) {
            int s0 = __shfl_sync(FULL, idx, j);
            int s1 = __shfl_sync(FULL, idx, j + 1);
            int s2 = __shfl_sync(FULL, idx, j + 2);
            int s3 = __shfl_sync(FULL, idx, j + 3);
            float4 v0 = __ldg(&u[s0 * 32 + lane]);
            float4 v1 = __ldg(&u[s1 * 32 + lane]);
            float4 v2 = __ldg(&u[s2 * 32 + lane]);
            float4 v3 = __ldg(&u[s3 * 32 + lane]);
            a0.x += v0.x; a0.y += v0.y; a0.z += v0.z; a0.w += v0.w;
            a1.x += v1.x; a1.y += v1.y; a1.z += v1.z; a1.w += v1.w;
            a2.x += v2.x; a2.y += v2.y; a2.z += v2.z; a2.w += v2.w;
            a3.x += v3.x; a3.y += v3.y; a3.z += v3.z; a3.w += v3.w;
        }
        for (; j < m; j++) {
            int s0 = __shfl_sync(FULL, idx, j);
            float4 v0 = __ldg(&u[s0 * 32 + lane]);
            a0.x += v0.x; a0.y += v0.y; a0.z += v0.z; a0.w += v0.w;
        }
    }
    const float inv = g_invdeg[node];
    float4 vv = __ldg(&v[node * 32 + lane]);
    float4 r = make_float4(fmaxf((a0.x + a1.x + a2.x + a3.x) * inv + vv.x, 0.f),
                           fmaxf((a0.y + a1.y + a2.y + a3.y) * inv + vv.y, 0.f),
                           fmaxf((a0.z + a1.z + a2.z + a3.z) * inv + vv.z, 0.f),
                           fmaxf((a0.w + a1.w + a2.w + a3.w) * inv + vv.w, 0.f));
    h[node * 32 + lane] = r;
}

// ---------------- layer 2 projections: [z | pre] = h @ [Wl2 | Wr2] ----------
__global__ __launch_bounds__(256, 1)
void k_gemmzp(const float* __restrict__ h,
              const float* __restrict__ Wl, const float* __restrict__ Wr,
              const float* __restrict__ bias,
              float* __restrict__ z, float* __restrict__ pre, int n)
{
    extern __shared__ float sm[];
    float* sW = sm;                // [128][128] = [Wl2 | Wr2]
    float* sA = sm + 128 * 128;    // [128][132]
    const int tid = threadIdx.x;
    const int row0 = blockIdx.x * 128;
    const int tx = tid & 15, ty = tid >> 4;

    float4* sW4 = (float4*)sW;
    const float4* Wl4 = (const float4*)Wl;
    const float4* Wr4 = (const float4*)Wr;
    for (int i = tid; i < 4096; i += 256) {
        int k = i >> 5, q = i & 31;
        float4 v = (q < 16) ? __ldg(&Wl4[k * 16 + q]) : __ldg(&Wr4[k * 16 + (q - 16)]);
        sW4[i] = v;
    }
    const float4* h4 = (const float4*)h;
    for (int i = tid; i < 4096; i += 256) {
        int r = i >> 5, q = i & 31;
        int gr = row0 + r;
        float4 v = make_float4(0.f, 0.f, 0.f, 0.f);
        if (gr < n) v = __ldg(&h4[gr * 32 + q]);
        *(float4*)&sA[r * 132 + q * 4] = v;
    }
    __syncthreads();

    unsigned long long acc[8][4];
#pragma unroll
    for (int i = 0; i < 8; i++)
#pragma unroll
        for (int j = 0; j < 4; j++) acc[i][j] = 0ull;

    const ulonglong2* sW2 = (const ulonglong2*)sW;
    const float* sa = &sA[ty * 8 * 132];
#pragma unroll 2
    for (int k = 0; k < 128; k++) {
        ulonglong2 wA = sW2[k * 32 + tx];
        ulonglong2 wB = sW2[k * 32 + 16 + tx];
#pragma unroll
        for (int i = 0; i < 8; i++) {
            unsigned long long aa = bcast2(sa[i * 132 + k]);
            acc[i][0] = fma2(aa, wA.x, acc[i][0]);
            acc[i][1] = fma2(aa, wA.y, acc[i][1]);
            acc[i][2] = fma2(aa, wB.x, acc[i][2]);
            acc[i][3] = fma2(aa, wB.y, acc[i][3]);
        }
    }

    float4 bv = __ldg(&((const float4*)bias)[tx]);
    float4* z4 = (float4*)z;
    float4* p4 = (float4*)pre;
#pragma unroll
    for (int i = 0; i < 8; i++) {
        int gr = row0 + ty * 8 + i;
        if (gr >= n) break;
        float2 p0 = unpack2(acc[i][0]), p1 = unpack2(acc[i][1]);
        float2 p2 = unpack2(acc[i][2]), p3 = unpack2(acc[i][3]);
        z4[gr * 16 + tx] = make_float4(p0.x, p0.y, p1.x, p1.y);
        p4[gr * 16 + tx] = make_float4(p2.x + bv.x, p2.y + bv.y,
                                       p3.x + bv.z, p3.y + bv.w);
    }
}

// ---------------- fused: out = log_softmax(mean_agg(z) + pre) ---------------
__global__ void k_agg64out(const float4* __restrict__ z, const float4* __restrict__ pre,
                           float4* __restrict__ out, int n)
{
    const int warp = blockIdx.x * (blockDim.x >> 5) + (threadIdx.x >> 5);
    const int lane = threadIdx.x & 31;
    const int half = lane >> 4, hl = lane & 15;
    const int node = warp * 2 + half;
    const bool valid = node < n;
    int beg = 0, cnt = 0;
    if (valid) {
        beg = g_rowstart[node];
        cnt = g_rowstart[node + 1] - beg;
    }
    int mx = cnt;
#pragma unroll
    for (int off = 16; off > 0; off >>= 1) mx = max(mx, __shfl_xor_sync(FULL, mx, off));

    float4 a0 = make_float4(0.f, 0.f, 0.f, 0.f);
    float4 a1 = make_float4(0.f, 0.f, 0.f, 0.f);
    for (int base = 0; base < mx; base += 16) {
        int idx = 0;
        if (base + hl < cnt) idx = __ldg(&g_srcs[beg + base + hl]);
        const int m = cnt - base;
#pragma unroll 4
        for (int j = 0; j < 16; j += 2) {
            int s0 = __shfl_sync(FULL, idx, half * 16 + j);
            int s1 = __shfl_sync(FULL, idx, half * 16 + j + 1);
            if (j < m) {
                float4 v = __ldg(&z[s0 * 16 + hl]);
                a0.x += v.x; a0.y += v.y; a0.z += v.z; a0.w += v.w;
            }
            if (j + 1 < m) {
                float4 v = __ldg(&z[s1 * 16 + hl]);
                a1.x += v.x; a1.y += v.y; a1.z += v.z; a1.w += v.w;
            }
        }
    }
    float4 p = valid ? __ldg(&pre[node * 16 + hl]) : make_float4(0.f, 0.f, 0.f, 0.f);
    const float inv = valid ? g_invdeg[node] : 1.0f;
    float4 v = make_float4((a0.x + a1.x) * inv + p.x, (a0.y + a1.y) * inv + p.y,
                           (a0.z + a1.z) * inv + p.z, (a0.w + a1.w) * inv + p.w);
    // log_softmax across the 64 values held by this half-warp (16 lanes x 4)
    float m4 = fmaxf(fmaxf(v.x, v.y), fmaxf(v.z, v.w));
#pragma unroll
    for (int off = 8; off > 0; off >>= 1) m4 = fmaxf(m4, __shfl_xor_sync(FULL, m4, off));
    float s = expf(v.x - m4) + expf(v.y - m4) + expf(v.z - m4) + expf(v.w - m4);
#pragma unroll
    for (int off = 8; off > 0; off >>= 1) s += __shfl_xor_sync(FULL, s, off);
    float lse = m4 + logf(s);
    if (valid)
        out[node * 16 + hl] = make_float4(v.x - lse, v.y - lse, v.z - lse, v.w - lse);
}

// ---------------- launch -----------------------------------------------------
extern "C" void kernel_launch(void* const* d_in, const int* in_sizes, int n_in,
                              void* d_out, int out_size)
{
    const float* x   = (const float*)d_in[0];
    const int*   ei  = (const int*)d_in[1];
    const float* Wl1 = (const float*)d_in[2];
    const float* Wr1 = (const float*)d_in[3];
    const float* b1  = (const float*)d_in[4];
    const float* Wl2 = (const float*)d_in[5];
    const float* Wr2 = (const float*)d_in[6];
    const float* b2  = (const float*)d_in[7];
    float* out = (float*)d_out;

    const int n = in_sizes[0] / 128;
    const int e = in_sizes[1] / 2;
    const int* src = ei;
    const int* dst = ei + e;

    // one-time host-side objects (created on the non-captured correctness call)
    static cudaStream_t s_side = nullptr;
    static cudaEvent_t ev_fork = nullptr, ev_join = nullptr;
    static bool attr_done = false;
    if (!s_side) {
        cudaStreamCreateWithFlags(&s_side, cudaStreamNonBlocking);
        cudaEventCreateWithFlags(&ev_fork, cudaEventDisableTiming);
        cudaEventCreateWithFlags(&ev_join, cudaEventDisableTiming);
    }
    if (!attr_done) {
        cudaFuncSetAttribute(k_xproj,  cudaFuncAttributeMaxDynamicSharedMemorySize, G_SMEM);
        cudaFuncSetAttribute(k_gemmzp, cudaFuncAttributeMaxDynamicSharedMemorySize, G_SMEM);
        attr_done = true;
    }

    void *p_u = nullptr, *p_v = nullptr, *p_h = nullptr, *p_z = nullptr, *p_pre = nullptr;
    cudaGetSymbolAddress(&p_u, g_u);
    cudaGetSymbolAddress(&p_v, g_v);
    cudaGetSymbolAddress(&p_h, g_h);
    cudaGetSymbolAddress(&p_z, g_z);
    cudaGetSymbolAddress(&p_pre, g_pre);
    float* ubuf = (float*)p_u;
    float* vbuf = (float*)p_v;
    float* hbuf = (float*)p_h;
    float* zbuf = (float*)p_z;
    float* pre  = (float*)p_pre;

    const int B = (n + 2047) / 2048;

    // fork: x projections on side stream, CSR build on main stream
    cudaEventRecord(ev_fork, 0);
    cudaStreamWaitEvent(s_side, ev_fork, 0);
    k_xproj<<<(n + 127) / 128, 256, G_SMEM, s_side>>>(x, Wl1, Wr1, b1, ubuf, vbuf, n);
    cudaEventRecord(ev_join, s_side);

    k_zero<<<(n + 1023) / 1024, 1024>>>(n);
    k_hist<<<(e + 255) / 256, 256>>>(dst, e);
    k_bsum<<<B, 512>>>(n);
    k_bscan<<<1, 64>>>(B, n, e);
    k_fill<<<B, 512>>>(n);
    k_scatter<<<(e + 255) / 256, 256>>>(src, dst, e);

    // join, then fused aggregation + layer-2
    cudaStreamWaitEvent(0, ev_join, 0);
    k_aggrelu<<<(n + 7) / 8, 256>>>((const float4*)ubuf, (const float4*)vbuf,
                                    (float4*)hbuf, n);
    k_gemmzp<<<(n + 127) / 128, 256, G_SMEM>>>(hbuf, Wl2, Wr2, b2, zbuf, pre, n);
    k_agg64out<<<(n + 15) / 16, 256>>>((const float4*)zbuf, (const float4*)pre,
                                       (float4*)out, n);
}

// round 6
// speedup vs baseline: 1.2458x; 1.2458x over previous
#include <cuda_runtime.h>
#include <cuda_fp16.h>
#include <math.h>

#define NMAX 100000
#define EMAX 1600000
#define FULL 0xffffffffu

// ---------------- scratch (static device globals; no allocations) ----------
__device__ int   g_count[NMAX];
__device__ int   g_rowstart[NMAX + 1];
__device__ int   g_cursor[NMAX];
__device__ int   g_srcs[EMAX];
__device__ float g_invdeg[NMAX];
__device__ int   g_bflag[64];
__device__ int   g_bincl[64];
__device__ uint4 g_u[NMAX * 16];     // x @ Wl1, fp16 packed (128 halves/row)
__device__ float g_v[NMAX * 128];    // x @ Wr1 + b1 (fp32)
__device__ float g_h[NMAX * 128];    // hidden features (fp32)
__device__ uint4 g_z[NMAX * 8];      // h @ Wl2, fp16 packed (64 halves/row)
__device__ float g_pre[NMAX * 64];   // h @ Wr2 + b2 (fp32)

// ---------------- helpers ---------------------------------------------------
__device__ __forceinline__ unsigned long long bcast2(float a) {
    unsigned long long d;
    unsigned int r = __float_as_uint(a);
    asm("mov.b64 %0, {%1, %1};" : "=l"(d) : "r"(r));
    return d;
}
__device__ __forceinline__ unsigned long long fma2(unsigned long long a,
                                                   unsigned long long b,
                                                   unsigned long long c) {
    unsigned long long d;
    asm("fma.rn.f32x2 %0, %1, %2, %3;" : "=l"(d) : "l"(a), "l"(b), "l"(c));
    return d;
}
__device__ __forceinline__ float2 unpack2(unsigned long long v) {
    unsigned int lo, hi;
    asm("mov.b64 {%0, %1}, %2;" : "=r"(lo), "=r"(hi) : "l"(v));
    return make_float2(__uint_as_float(lo), __uint_as_float(hi));
}
__device__ __forceinline__ unsigned int packh2(float a, float b) {
    __half2 h = __floats2half2_rn(a, b);
    return *(unsigned int*)&h;
}
__device__ __forceinline__ void acc8(float* a, uint4 w) {
    float2 f0 = __half22float2(*(__half2*)&w.x);
    float2 f1 = __half22float2(*(__half2*)&w.y);
    float2 f2 = __half22float2(*(__half2*)&w.z);
    float2 f3 = __half22float2(*(__half2*)&w.w);
    a[0] += f0.x; a[1] += f0.y; a[2] += f1.x; a[3] += f1.y;
    a[4] += f2.x; a[5] += f2.y; a[6] += f3.x; a[7] += f3.y;
}

// ---------------- CSR build -------------------------------------------------
__global__ void k_zero(int n) {
    int i = blockIdx.x * blockDim.x + threadIdx.x;
    if (i < n) g_count[i] = 0;
    if (i < 64) g_bflag[i] = 0;
}

__global__ void k_hist(const int* __restrict__ dst, int e) {
    int i = blockIdx.x * blockDim.x + threadIdx.x;
    if (i < e) atomicAdd(&g_count[dst[i]], 1);
}

// one-kernel scan + fill: per-block scan, decoupled chained lookback over blocks
__global__ void k_scanfill(int n, int e) {
    const int tid = threadIdx.x;
    const int lane = tid & 31, wid = tid >> 5;
    const int b = blockIdx.x;
    const int gbase = b * 2048 + tid * 4;
    int c[4];
    int s = 0;
#pragma unroll
    for (int j = 0; j < 4; j++) {
        c[j] = (gbase + j < n) ? g_count[gbase + j] : 0;
        s += c[j];
    }
    int incl = s;
#pragma unroll
    for (int off = 1; off < 32; off <<= 1) {
        int t = __shfl_up_sync(FULL, incl, off);
        if (lane >= off) incl += t;
    }
    __shared__ int wsum[16];
    __shared__ int sprev;
    if (lane == 31) wsum[wid] = incl;
    __syncthreads();
    if (tid < 16) {
        int v = wsum[tid];
#pragma unroll
        for (int off = 1; off < 16; off <<= 1) {
            int t = __shfl_up_sync(0xffffu, v, off);
            if (tid >= off) v += t;
        }
        wsum[tid] = v;
    }
    __syncthreads();
    if (tid == 0) {
        int prev = 0;
        if (b > 0) {
            while (atomicAdd(&g_bflag[b - 1], 0) == 0) {}
            prev = atomicAdd(&g_bincl[b - 1], 0);   // L2-coherent read
        }
        g_bincl[b] = prev + wsum[15];
        __threadfence();
        atomicExch(&g_bflag[b], 1);
        sprev = prev;
        if (b == 0) g_rowstart[n] = e;
    }
    __syncthreads();
    int base = sprev + (incl - s) + (wid ? wsum[wid - 1] : 0);
#pragma unroll
    for (int j = 0; j < 4; j++) {
        if (gbase + j < n) {
            g_rowstart[gbase + j] = base;
            g_cursor[gbase + j] = base;
            g_invdeg[gbase + j] = 1.0f / fmaxf((float)c[j], 1.0f);
            base += c[j];
        }
    }
}

__global__ void k_scatter(const int* __restrict__ src, const int* __restrict__ dst, int e) {
    int i = blockIdx.x * blockDim.x + threadIdx.x;
    if (i < e) {
        int pos = atomicAdd(&g_cursor[dst[i]], 1);
        g_srcs[pos] = src[i];
    }
}

// ---------------- x projections: u = fp16(x@Wl1), v = x@Wr1 + b1 ------------
#define G_SMEM ((128 * 128 + 128 * 132) * 4)
__global__ __launch_bounds__(256, 1)
void k_xproj(const float* __restrict__ x,
             const float* __restrict__ Wl, const float* __restrict__ Wr,
             const float* __restrict__ bias,
             uint2* __restrict__ u, float* __restrict__ v, int n)
{
    extern __shared__ float sm[];
    float* sW = sm;                // [128][128]
    float* sA = sm + 128 * 128;    // [128][132]
    const int tid = threadIdx.x;
    const int row0 = blockIdx.x * 128;
    const int tx = tid & 15, ty = tid >> 4;

    const float4* x4 = (const float4*)x;
    for (int i = tid; i < 4096; i += 256) {
        int r = i >> 5, q = i & 31;
        int gr = row0 + r;
        float4 vv = make_float4(0.f, 0.f, 0.f, 0.f);
        if (gr < n) vv = __ldg(&x4[gr * 32 + q]);
        *(float4*)&sA[r * 132 + q * 4] = vv;
    }

    float4* sW4 = (float4*)sW;
    const float4* b4 = (const float4*)bias;
    const float4 bv0 = __ldg(&b4[tx]);
    const float4 bv1 = __ldg(&b4[16 + tx]);

#pragma unroll 1
    for (int half = 0; half < 2; half++) {
        const float4* Wsrc = (const float4*)(half ? Wr : Wl);
        for (int i = tid; i < 4096; i += 256) sW4[i] = __ldg(&Wsrc[i]);
        __syncthreads();

        unsigned long long acc[8][4];
#pragma unroll
        for (int i = 0; i < 8; i++)
#pragma unroll
            for (int j = 0; j < 4; j++) acc[i][j] = 0ull;

        const ulonglong2* sW2 = (const ulonglong2*)sW;
        const float* sa = &sA[ty * 8 * 132];
#pragma unroll 2
        for (int k = 0; k < 128; k++) {
            ulonglong2 wA = sW2[k * 32 + tx];
            ulonglong2 wB = sW2[k * 32 + 16 + tx];
#pragma unroll
            for (int i = 0; i < 8; i++) {
                unsigned long long aa = bcast2(sa[i * 132 + k]);
                acc[i][0] = fma2(aa, wA.x, acc[i][0]);
                acc[i][1] = fma2(aa, wA.y, acc[i][1]);
                acc[i][2] = fma2(aa, wB.x, acc[i][2]);
                acc[i][3] = fma2(aa, wB.y, acc[i][3]);
            }
        }
        __syncthreads();

#pragma unroll
        for (int i = 0; i < 8; i++) {
            int gr = row0 + ty * 8 + i;
            if (gr >= n) break;
            float2 p0 = unpack2(acc[i][0]), p1 = unpack2(acc[i][1]);
            float2 p2 = unpack2(acc[i][2]), p3 = unpack2(acc[i][3]);
            if (half) {
                float4* v4 = (float4*)v;
                v4[gr * 32 + tx]      = make_float4(p0.x + bv0.x, p0.y + bv0.y,
                                                    p1.x + bv0.z, p1.y + bv0.w);
                v4[gr * 32 + 16 + tx] = make_float4(p2.x + bv1.x, p2.y + bv1.y,
                                                    p3.x + bv1.z, p3.y + bv1.w);
            } else {
                u[gr * 32 + tx]      = make_uint2(packh2(p0.x, p0.y), packh2(p1.x, p1.y));
                u[gr * 32 + 16 + tx] = make_uint2(packh2(p2.x, p2.y), packh2(p3.x, p3.y));
            }
        }
    }
}

// ---------------- fused: h = relu(mean_agg(u_fp16) + v) ---------------------
// warp per node; pair = lane>>4 handles neighbor j+pair, c = lane&15 picks
// 8 contiguous fp16 features (16B). 2 neighbors per load step.
__global__ void k_aggrelu(const uint4* __restrict__ u, const float4* __restrict__ v,
                          float4* __restrict__ h, int n)
{
    int node = blockIdx.x * (blockDim.x >> 5) + (threadIdx.x >> 5);
    if (node >= n) return;
    const int lane = threadIdx.x & 31;
    const int pair = lane >> 4, c = lane & 15;
    const int beg = g_rowstart[node];
    const int cnt = g_rowstart[node + 1] - beg;

    float a0[8] = {0,0,0,0,0,0,0,0};
    float a1[8] = {0,0,0,0,0,0,0,0};

    for (int base = 0; base < cnt; base += 32) {
        const int m = min(32, cnt - base);
        int idx = (lane < m) ? __ldg(&g_srcs[beg + base + lane]) : 0;
        int j = 0;
        for (; j + 3 < m; j += 4) {
            int s0 = __shfl_sync(FULL, idx, j + pair);
            int s1 = __shfl_sync(FULL, idx, j + 2 + pair);
            uint4 w0 = __ldg(&u[s0 * 16 + c]);
            uint4 w1 = __ldg(&u[s1 * 16 + c]);
            acc8(a0, w0);
            acc8(a1, w1);
        }
        for (; j < m; j += 2) {
            int s0 = __shfl_sync(FULL, idx, (j + pair) & 31);
            if (j + pair < m) {
                uint4 w0 = __ldg(&u[s0 * 16 + c]);
                acc8(a0, w0);
            }
        }
    }
#pragma unroll
    for (int i = 0; i < 8; i++) {
        a0[i] += a1[i];
        a0[i] += __shfl_xor_sync(FULL, a0[i], 16);
    }
    const float inv = g_invdeg[node];
    float4 vv = __ldg(&v[node * 32 + c * 2 + pair]);
    const int k0 = pair * 4;
    h[node * 32 + c * 2 + pair] =
        make_float4(fmaxf(a0[k0 + 0] * inv + vv.x, 0.f),
                    fmaxf(a0[k0 + 1] * inv + vv.y, 0.f),
                    fmaxf(a0[k0 + 2] * inv + vv.z, 0.f),
                    fmaxf(a0[k0 + 3] * inv + vv.w, 0.f));
}

// ---------------- layer 2 projections: z = fp16(h@Wl2), pre = h@Wr2 + b2 ----
__global__ __launch_bounds__(256, 1)
void k_gemmzp(const float* __restrict__ h,
              const float* __restrict__ Wl, const float* __restrict__ Wr,
              const float* __restrict__ bias,
              uint2* __restrict__ z, float* __restrict__ pre, int n)
{
    extern __shared__ float sm[];
    float* sW = sm;                // [128][128] = [Wl2 | Wr2]
    float* sA = sm + 128 * 128;    // [128][132]
    const int tid = threadIdx.x;
    const int row0 = blockIdx.x * 128;
    const int tx = tid & 15, ty = tid >> 4;

    float4* sW4 = (float4*)sW;
    const float4* Wl4 = (const float4*)Wl;
    const float4* Wr4 = (const float4*)Wr;
    for (int i = tid; i < 4096; i += 256) {
        int k = i >> 5, q = i & 31;
        float4 v = (q < 16) ? __ldg(&Wl4[k * 16 + q]) : __ldg(&Wr4[k * 16 + (q - 16)]);
        sW4[i] = v;
    }
    const float4* h4 = (const float4*)h;
    for (int i = tid; i < 4096; i += 256) {
        int r = i >> 5, q = i & 31;
        int gr = row0 + r;
        float4 v = make_float4(0.f, 0.f, 0.f, 0.f);
        if (gr < n) v = __ldg(&h4[gr * 32 + q]);
        *(float4*)&sA[r * 132 + q * 4] = v;
    }
    __syncthreads();

    unsigned long long acc[8][4];
#pragma unroll
    for (int i = 0; i < 8; i++)
#pragma unroll
        for (int j = 0; j < 4; j++) acc[i][j] = 0ull;

    const ulonglong2* sW2 = (const ulonglong2*)sW;
    const float* sa = &sA[ty * 8 * 132];
#pragma unroll 2
    for (int k = 0; k < 128; k++) {
        ulonglong2 wA = sW2[k * 32 + tx];
        ulonglong2 wB = sW2[k * 32 + 16 + tx];
#pragma unroll
        for (int i = 0; i < 8; i++) {
            unsigned long long aa = bcast2(sa[i * 132 + k]);
            acc[i][0] = fma2(aa, wA.x, acc[i][0]);
            acc[i][1] = fma2(aa, wA.y, acc[i][1]);
            acc[i][2] = fma2(aa, wB.x, acc[i][2]);
            acc[i][3] = fma2(aa, wB.y, acc[i][3]);
        }
    }

    float4 bv = __ldg(&((const float4*)bias)[tx]);
    float4* p4 = (float4*)pre;
#pragma unroll
    for (int i = 0; i < 8; i++) {
        int gr = row0 + ty * 8 + i;
        if (gr >= n) break;
        float2 p0 = unpack2(acc[i][0]), p1 = unpack2(acc[i][1]);
        float2 p2 = unpack2(acc[i][2]), p3 = unpack2(acc[i][3]);
        z[gr * 16 + tx] = make_uint2(packh2(p0.x, p0.y), packh2(p1.x, p1.y));
        p4[gr * 16 + tx] = make_float4(p2.x + bv.x, p2.y + bv.y,
                                       p3.x + bv.z, p3.y + bv.w);
    }
}

// ---------------- fused: out = log_softmax(mean_agg(z_fp16) + pre) ----------
// warp per node; quad = lane>>3 handles neighbor j+quad, c = lane&7 picks
// 8 contiguous fp16 features. 4 neighbors per load step.
__global__ void k_agg64out(const uint4* __restrict__ z, const float4* __restrict__ pre,
                           float4* __restrict__ out, int n)
{
    int node = blockIdx.x * (blockDim.x >> 5) + (threadIdx.x >> 5);
    if (node >= n) return;
    const int lane = threadIdx.x & 31;
    const int quad = lane >> 3, c = lane & 7;
    const int beg = g_rowstart[node];
    const int cnt = g_rowstart[node + 1] - beg;

    float a0[8] = {0,0,0,0,0,0,0,0};
    float a1[8] = {0,0,0,0,0,0,0,0};

    for (int base = 0; base < cnt; base += 32) {
        const int m = min(32, cnt - base);
        int idx = (lane < m) ? __ldg(&g_srcs[beg + base + lane]) : 0;
        int j = 0;
        for (; j + 7 < m; j += 8) {
            int s0 = __shfl_sync(FULL, idx, j + quad);
            int s1 = __shfl_sync(FULL, idx, j + 4 + quad);
            uint4 w0 = __ldg(&z[s0 * 8 + c]);
            uint4 w1 = __ldg(&z[s1 * 8 + c]);
            acc8(a0, w0);
            acc8(a1, w1);
        }
        for (; j < m; j += 4) {
            int s0 = __shfl_sync(FULL, idx, (j + quad) & 31);
            if (j + quad < m) {
                uint4 w0 = __ldg(&z[s0 * 8 + c]);
                acc8(a0, w0);
            }
        }
    }
#pragma unroll
    for (int i = 0; i < 8; i++) {
        a0[i] += a1[i];
        a0[i] += __shfl_xor_sync(FULL, a0[i], 8);
        a0[i] += __shfl_xor_sync(FULL, a0[i], 16);
    }
    const float inv = g_invdeg[node];
    float4 p0 = __ldg(&pre[node * 16 + c * 2]);
    float4 p1 = __ldg(&pre[node * 16 + c * 2 + 1]);
    float vv[8];
    vv[0] = a0[0] * inv + p0.x; vv[1] = a0[1] * inv + p0.y;
    vv[2] = a0[2] * inv + p0.z; vv[3] = a0[3] * inv + p0.w;
    vv[4] = a0[4] * inv + p1.x; vv[5] = a0[5] * inv + p1.y;
    vv[6] = a0[6] * inv + p1.z; vv[7] = a0[7] * inv + p1.w;

    float m8 = vv[0];
#pragma unroll
    for (int i = 1; i < 8; i++) m8 = fmaxf(m8, vv[i]);
#pragma unroll
    for (int off = 4; off > 0; off >>= 1) m8 = fmaxf(m8, __shfl_xor_sync(FULL, m8, off));
    float s = 0.f;
#pragma unroll
    for (int i = 0; i < 8; i++) s += expf(vv[i] - m8);
#pragma unroll
    for (int off = 4; off > 0; off >>= 1) s += __shfl_xor_sync(FULL, s, off);
    float lse = m8 + logf(s);

    if (quad < 2) {
        const int k0 = quad * 4;
        out[node * 16 + c * 2 + quad] =
            make_float4(vv[k0 + 0] - lse, vv[k0 + 1] - lse,
                        vv[k0 + 2] - lse, vv[k0 + 3] - lse);
    }
}

// ---------------- launch -----------------------------------------------------
extern "C" void kernel_launch(void* const* d_in, const int* in_sizes, int n_in,
                              void* d_out, int out_size)
{
    const float* x   = (const float*)d_in[0];
    const int*   ei  = (const int*)d_in[1];
    const float* Wl1 = (const float*)d_in[2];
    const float* Wr1 = (const float*)d_in[3];
    const float* b1  = (const float*)d_in[4];
    const float* Wl2 = (const float*)d_in[5];
    const float* Wr2 = (const float*)d_in[6];
    const float* b2  = (const float*)d_in[7];
    float* out = (float*)d_out;

    const int n = in_sizes[0] / 128;
    const int e = in_sizes[1] / 2;
    const int* src = ei;
    const int* dst = ei + e;

    static bool attr_done = false;
    if (!attr_done) {
        cudaFuncSetAttribute(k_xproj,  cudaFuncAttributeMaxDynamicSharedMemorySize, G_SMEM);
        cudaFuncSetAttribute(k_gemmzp, cudaFuncAttributeMaxDynamicSharedMemorySize, G_SMEM);
        attr_done = true;
    }

    void *p_u = nullptr, *p_v = nullptr, *p_h = nullptr, *p_z = nullptr, *p_pre = nullptr;
    cudaGetSymbolAddress(&p_u, g_u);
    cudaGetSymbolAddress(&p_v, g_v);
    cudaGetSymbolAddress(&p_h, g_h);
    cudaGetSymbolAddress(&p_z, g_z);
    cudaGetSymbolAddress(&p_pre, g_pre);

    const int B = (n + 2047) / 2048;

    k_zero<<<(n + 1023) / 1024, 1024>>>(n);
    k_hist<<<(e + 255) / 256, 256>>>(dst, e);
    k_scanfill<<<B, 512>>>(n, e);
    k_xproj<<<(n + 127) / 128, 256, G_SMEM>>>(x, Wl1, Wr1, b1,
                                              (uint2*)p_u, (float*)p_v, n);
    k_scatter<<<(e + 255) / 256, 256>>>(src, dst, e);
    k_aggrelu<<<(n + 7) / 8, 256>>>((const uint4*)p_u, (const float4*)p_v,
                                    (float4*)p_h, n);
    k_gemmzp<<<(n + 127) / 128, 256, G_SMEM>>>((const float*)p_h, Wl2, Wr2, b2,
                                               (uint2*)p_z, (float*)p_pre, n);
    k_agg64out<<<(n + 7) / 8, 256>>>((const uint4*)p_z, (const float4*)p_pre,
                                     (float4*)out, n);
}

// round 11
// speedup vs baseline: 1.6422x; 1.3182x over previous
#include <cuda_runtime.h>
#include <cuda_fp16.h>
#include <stdint.h>
#include <math.h>

#define NMAX 100000
#define EMAX 1600000
#define FULL 0xffffffffu

// ---------------- scratch (static device globals; no allocations) ----------
__device__ int   g_count[NMAX];
__device__ int   g_rowstart[NMAX + 1];
__device__ int   g_cursor[NMAX];
__device__ int   g_srcs[EMAX];
__device__ float g_invdeg[NMAX];
__device__ int   g_bflag[64];
__device__ int   g_bincl[64];
__device__ uint4 g_u[NMAX * 16];     // x @ Wl1, fp16 packed (128 halves/row)
__device__ float g_v[NMAX * 128];    // x @ Wr1 + b1 (fp32)
__device__ uint2 g_hh[NMAX * 32];    // hidden features, fp16 packed (128/row)
__device__ uint4 g_z[NMAX * 8];      // h @ Wl2, fp16 packed (64 halves/row)
__device__ float g_pre[NMAX * 64];   // h @ Wr2 + b2 (fp32)
__device__ uint4 g_w1h[256 * 16];    // [Wl1|Wr1]^T fp16: [n=256][k=128]
__device__ uint4 g_w2h[128 * 16];    // [Wl2|Wr2]^T fp16: [n=128][k=128]

// ---------------- helpers ---------------------------------------------------
__device__ __forceinline__ uint32_t smem_u32(const void* p) {
    uint32_t a;
    asm("{ .reg .u64 t; cvta.to.shared.u64 t, %1; cvt.u32.u64 %0, t; }" : "=r"(a) : "l"(p));
    return a;
}
__device__ __forceinline__ unsigned int packh2(float a, float b) {
    __half2 h = __floats2half2_rn(a, b);
    return *(unsigned int*)&h;
}
__device__ __forceinline__ void acc8(float* a, uint4 w) {
    float2 f0 = __half22float2(*(__half2*)&w.x);
    float2 f1 = __half22float2(*(__half2*)&w.y);
    float2 f2 = __half22float2(*(__half2*)&w.z);
    float2 f3 = __half22float2(*(__half2*)&w.w);
    a[0] += f0.x; a[1] += f0.y; a[2] += f1.x; a[3] += f1.y;
    a[4] += f2.x; a[5] += f2.y; a[6] += f3.x; a[7] += f3.y;
}

#define LDSM4(r, addr)                                                                \
    asm volatile("ldmatrix.sync.aligned.m8n8.x4.shared.b16 {%0,%1,%2,%3}, [%4];"      \
        : "=r"((r)[0]), "=r"((r)[1]), "=r"((r)[2]), "=r"((r)[3]) : "r"(addr))

#define MMA16816(d, a, b0, b1)                                                        \
    asm volatile("mma.sync.aligned.m16n8k16.row.col.f32.f16.f16.f32 "                 \
        "{%0,%1,%2,%3}, {%4,%5,%6,%7}, {%8,%9}, {%0,%1,%2,%3};"                       \
        : "+f"((d)[0]), "+f"((d)[1]), "+f"((d)[2]), "+f"((d)[3])                      \
        : "r"((a)[0]), "r"((a)[1]), "r"((a)[2]), "r"((a)[3]), "r"(b0), "r"(b1))

// ---------------- CSR build -------------------------------------------------
__global__ void k_zero(int n) {
    int i = blockIdx.x * blockDim.x + threadIdx.x;
    if (i < n) g_count[i] = 0;
    if (i < 64) g_bflag[i] = 0;
}

__global__ void k_hist(const int* __restrict__ dst, int e) {
    int i = blockIdx.x * blockDim.x + threadIdx.x;
    if (i < e) atomicAdd(&g_count[dst[i]], 1);
}

__global__ void k_scanfill(int n, int e) {
    const int tid = threadIdx.x;
    const int lane = tid & 31, wid = tid >> 5;
    const int b = blockIdx.x;
    const int gbase = b * 2048 + tid * 4;
    int c[4];
    int s = 0;
#pragma unroll
    for (int j = 0; j < 4; j++) {
        c[j] = (gbase + j < n) ? g_count[gbase + j] : 0;
        s += c[j];
    }
    int incl = s;
#pragma unroll
    for (int off = 1; off < 32; off <<= 1) {
        int t = __shfl_up_sync(FULL, incl, off);
        if (lane >= off) incl += t;
    }
    __shared__ int wsum[16];
    __shared__ int sprev;
    if (lane == 31) wsum[wid] = incl;
    __syncthreads();
    if (tid < 16) {
        int v = wsum[tid];
#pragma unroll
        for (int off = 1; off < 16; off <<= 1) {
            int t = __shfl_up_sync(0xffffu, v, off);
            if (tid >= off) v += t;
        }
        wsum[tid] = v;
    }
    __syncthreads();
    if (tid == 0) {
        int prev = 0;
        if (b > 0) {
            while (atomicAdd(&g_bflag[b - 1], 0) == 0) {}
            prev = atomicAdd(&g_bincl[b - 1], 0);
        }
        g_bincl[b] = prev + wsum[15];
        __threadfence();
        atomicExch(&g_bflag[b], 1);
        sprev = prev;
        if (b == 0) g_rowstart[n] = e;
    }
    __syncthreads();
    int base = sprev + (incl - s) + (wid ? wsum[wid - 1] : 0);
#pragma unroll
    for (int j = 0; j < 4; j++) {
        if (gbase + j < n) {
            g_rowstart[gbase + j] = base;
            g_cursor[gbase + j] = base;
            g_invdeg[gbase + j] = 1.0f / fmaxf((float)c[j], 1.0f);
            base += c[j];
        }
    }
}

__global__ void k_scatter(const int* __restrict__ src, const int* __restrict__ dst, int e) {
    int i = blockIdx.x * blockDim.x + threadIdx.x;
    if (i < e) {
        int pos = atomicAdd(&g_cursor[dst[i]], 1);
        g_srcs[pos] = src[i];
    }
}

// ---------------- weight transpose+convert to fp16 --------------------------
__global__ void k_cvtw(const float* __restrict__ Wl1, const float* __restrict__ Wr1,
                       const float* __restrict__ Wl2, const float* __restrict__ Wr2) {
    int i = blockIdx.x * blockDim.x + threadIdx.x;
    __half* w1 = (__half*)g_w1h;
    __half* w2 = (__half*)g_w2h;
    if (i < 256 * 128) {
        int nn = i >> 7, k = i & 127;
        float v = (nn < 128) ? Wl1[k * 128 + nn] : Wr1[k * 128 + (nn - 128)];
        w1[i] = __float2half_rn(v);
    } else if (i < 256 * 128 + 128 * 128) {
        int j = i - 256 * 128;
        int nn = j >> 7, k = j & 127;
        float v = (nn < 64) ? Wl2[k * 64 + nn] : Wr2[k * 64 + (nn - 64)];
        w2[j] = __float2half_rn(v);
    }
}

// ---------------- mma.sync GEMM 1: [u | v] = x @ [Wl1 | Wr1] ----------------
// CTA tile M=128, N=256, K=128. 8 warps = 4(m) x 2(n); warp = 32 rows x 128 cols.
// smem: A[128][136] halves (34816B) + WT[256][136] halves (69632B) = 104448B.
// Row stride 272B = 17 x 16B (odd) -> conflict-free ldmatrix.
#define XP_SMEM (34816 + 69632)
__global__ __launch_bounds__(256, 2)
void mma_xproj(const float* __restrict__ x, const float* __restrict__ bias,
               uint32_t* __restrict__ u32, float2* __restrict__ v2, int n)
{
    extern __shared__ char smem[];
    const uint32_t sbA = smem_u32(smem);
    const uint32_t sbB = sbA + 34816;
    const int tid = threadIdx.x, wid = tid >> 5, lane = tid & 31;
    const int row0T = blockIdx.x * 128;

    // stage WT (256 rows x 16 x 16B)
    {
        const uint4* wt = (const uint4*)g_w1h;
        uint4* sB4 = (uint4*)(smem + 34816);
        for (int i = tid; i < 4096; i += 256) {
            int r = i >> 4, hc = i & 15;
            sB4[r * 17 + hc] = __ldg(&wt[r * 16 + hc]);
        }
    }
    // stage A: x fp32 -> fp16
    {
        uint4* sA4 = (uint4*)smem;
        const float4* x4 = (const float4*)x;
        for (int i = tid; i < 2048; i += 256) {
            int r = i >> 4, hc = i & 15;
            int gr = row0T + r;
            uint4 val = make_uint4(0, 0, 0, 0);
            if (gr < n) {
                float4 f0 = __ldg(&x4[gr * 32 + hc * 2]);
                float4 f1 = __ldg(&x4[gr * 32 + hc * 2 + 1]);
                val = make_uint4(packh2(f0.x, f0.y), packh2(f0.z, f0.w),
                                 packh2(f1.x, f1.y), packh2(f1.z, f1.w));
            }
            sA4[r * 17 + hc] = val;
        }
    }
    __syncthreads();

    const int wm = wid & 3, gq = wid >> 2;   // m-slot, n-group (0:u, 1:v)
    const int gid = lane >> 2, tig = lane & 3;

    float acc[2][16][4];
#pragma unroll
    for (int mt = 0; mt < 2; mt++)
#pragma unroll
        for (int nt = 0; nt < 16; nt++)
#pragma unroll
            for (int q = 0; q < 4; q++) acc[mt][nt][q] = 0.f;

    const uint32_t aRow = (uint32_t)(wm * 32 + (lane & 15));
    const uint32_t aColOff = 8u * (lane >> 4);
    const uint32_t bRow = (uint32_t)(gq * 128 + (lane & 7) + 8 * (lane >> 4));
    const uint32_t bColOff = 8u * ((lane >> 3) & 1);

#pragma unroll
    for (int k0 = 0; k0 < 8; k0++) {
        const uint32_t kk = (uint32_t)k0 * 16;
        uint32_t a[2][4];
#pragma unroll
        for (int mt = 0; mt < 2; mt++) {
            uint32_t addr = sbA + ((aRow + mt * 16) * 136 + kk + aColOff) * 2;
            LDSM4(a[mt], addr);
        }
#pragma unroll
        for (int np = 0; np < 8; np++) {
            uint32_t addr = sbB + ((bRow + np * 16) * 136 + kk + bColOff) * 2;
            uint32_t b[4];
            LDSM4(b, addr);
#pragma unroll
            for (int mt = 0; mt < 2; mt++) {
                MMA16816(acc[mt][np * 2],     a[mt], b[0], b[1]);
                MMA16816(acc[mt][np * 2 + 1], a[mt], b[2], b[3]);
            }
        }
    }

    // epilogue
#pragma unroll
    for (int mt = 0; mt < 2; mt++) {
        int r0 = row0T + wm * 32 + mt * 16 + gid;
        int r1 = r0 + 8;
        if (gq == 0) {
#pragma unroll
            for (int nt = 0; nt < 16; nt++) {
                if (r0 < n) u32[r0 * 64 + nt * 4 + tig] = packh2(acc[mt][nt][0], acc[mt][nt][1]);
                if (r1 < n) u32[r1 * 64 + nt * 4 + tig] = packh2(acc[mt][nt][2], acc[mt][nt][3]);
            }
        } else {
            const float2* b2 = (const float2*)bias;
#pragma unroll
            for (int nt = 0; nt < 16; nt++) {
                float2 bb = __ldg(&b2[nt * 4 + tig]);
                if (r0 < n) v2[r0 * 64 + nt * 4 + tig] =
                    make_float2(acc[mt][nt][0] + bb.x, acc[mt][nt][1] + bb.y);
                if (r1 < n) v2[r1 * 64 + nt * 4 + tig] =
                    make_float2(acc[mt][nt][2] + bb.x, acc[mt][nt][3] + bb.y);
            }
        }
    }
}

// ---------------- mma.sync GEMM 2: [z | pre] = h @ [Wl2 | Wr2] --------------
// CTA tile M=128, N=128, K=128. 8 warps = 4(m) x 2(n); warp = 32 rows x 64 cols.
#define ZP_SMEM (34816 + 34816)
__global__ __launch_bounds__(256, 2)
void mma_zp(const float* __restrict__ bias,
            uint32_t* __restrict__ z32, float2* __restrict__ pre2, int n)
{
    extern __shared__ char smem[];
    const uint32_t sbA = smem_u32(smem);
    const uint32_t sbB = sbA + 34816;
    const int tid = threadIdx.x, wid = tid >> 5, lane = tid & 31;
    const int row0T = blockIdx.x * 128;

    {
        const uint4* wt = (const uint4*)g_w2h;
        uint4* sB4 = (uint4*)(smem + 34816);
        for (int i = tid; i < 2048; i += 256) {
            int r = i >> 4, hc = i & 15;
            sB4[r * 17 + hc] = __ldg(&wt[r * 16 + hc]);
        }
    }
    {
        uint4* sA4 = (uint4*)smem;
        const uint4* h16 = (const uint4*)g_hh;
        for (int i = tid; i < 2048; i += 256) {
            int r = i >> 4, hc = i & 15;
            int gr = row0T + r;
            uint4 val = make_uint4(0, 0, 0, 0);
            if (gr < n) val = __ldg(&h16[gr * 16 + hc]);
            sA4[r * 17 + hc] = val;
        }
    }
    __syncthreads();

    const int wm = wid & 3, gq = wid >> 2;   // n-group 0: z, 1: pre
    const int gid = lane >> 2, tig = lane & 3;

    float acc[2][8][4];
#pragma unroll
    for (int mt = 0; mt < 2; mt++)
#pragma unroll
        for (int nt = 0; nt < 8; nt++)
#pragma unroll
            for (int q = 0; q < 4; q++) acc[mt][nt][q] = 0.f;

    const uint32_t aRow = (uint32_t)(wm * 32 + (lane & 15));
    const uint32_t aColOff = 8u * (lane >> 4);
    const uint32_t bRow = (uint32_t)(gq * 64 + (lane & 7) + 8 * (lane >> 4));
    const uint32_t bColOff = 8u * ((lane >> 3) & 1);

#pragma unroll
    for (int k0 = 0; k0 < 8; k0++) {
        const uint32_t kk = (uint32_t)k0 * 16;
        uint32_t a[2][4];
#pragma unroll
        for (int mt = 0; mt < 2; mt++) {
            uint32_t addr = sbA + ((aRow + mt * 16) * 136 + kk + aColOff) * 2;
            LDSM4(a[mt], addr);
        }
#pragma unroll
        for (int np = 0; np < 4; np++) {
            uint32_t addr = sbB + ((bRow + np * 16) * 136 + kk + bColOff) * 2;
            uint32_t b[4];
            LDSM4(b, addr);
#pragma unroll
            for (int mt = 0; mt < 2; mt++) {
                MMA16816(acc[mt][np * 2],     a[mt], b[0], b[1]);
                MMA16816(acc[mt][np * 2 + 1], a[mt], b[2], b[3]);
            }
        }
    }

#pragma unroll
    for (int mt = 0; mt < 2; mt++) {
        int r0 = row0T + wm * 32 + mt * 16 + gid;
        int r1 = r0 + 8;
        if (gq == 0) {
#pragma unroll
            for (int nt = 0; nt < 8; nt++) {
                if (r0 < n) z32[r0 * 32 + nt * 4 + tig] = packh2(acc[mt][nt][0], acc[mt][nt][1]);
                if (r1 < n) z32[r1 * 32 + nt * 4 + tig] = packh2(acc[mt][nt][2], acc[mt][nt][3]);
            }
        } else {
            const float2* b2 = (const float2*)bias;
#pragma unroll
            for (int nt = 0; nt < 8; nt++) {
                float2 bb = __ldg(&b2[nt * 4 + tig]);
                if (r0 < n) pre2[r0 * 32 + nt * 4 + tig] =
                    make_float2(acc[mt][nt][0] + bb.x, acc[mt][nt][1] + bb.y);
                if (r1 < n) pre2[r1 * 32 + nt * 4 + tig] =
                    make_float2(acc[mt][nt][2] + bb.x, acc[mt][nt][3] + bb.y);
            }
        }
    }
}

// ---------------- fused: h = fp16(relu(mean_agg(u_fp16) + v)) ---------------
__global__ void k_aggrelu(const uint4* __restrict__ u, const float4* __restrict__ v,
                          uint2* __restrict__ hh, int n)
{
    int node = blockIdx.x * (blockDim.x >> 5) + (threadIdx.x >> 5);
    if (node >= n) return;
    const int lane = threadIdx.x & 31;
    const int pair = lane >> 4, c = lane & 15;
    const int beg = g_rowstart[node];
    const int cnt = g_rowstart[node + 1] - beg;

    float a0[8] = {0,0,0,0,0,0,0,0};
    float a1[8] = {0,0,0,0,0,0,0,0};

    for (int base = 0; base < cnt; base += 32) {
        const int m = min(32, cnt - base);
        int idx = (lane < m) ? __ldg(&g_srcs[beg + base + lane]) : 0;
        int j = 0;
        for (; j + 3 < m; j += 4) {
            int s0 = __shfl_sync(FULL, idx, j + pair);
            int s1 = __shfl_sync(FULL, idx, j + 2 + pair);
            uint4 w0 = __ldg(&u[s0 * 16 + c]);
            uint4 w1 = __ldg(&u[s1 * 16 + c]);
            acc8(a0, w0);
            acc8(a1, w1);
        }
        for (; j < m; j += 2) {
            int s0 = __shfl_sync(FULL, idx, (j + pair) & 31);
            if (j + pair < m) {
                uint4 w0 = __ldg(&u[s0 * 16 + c]);
                acc8(a0, w0);
            }
        }
    }
#pragma unroll
    for (int i = 0; i < 8; i++) {
        a0[i] += a1[i];
        a0[i] += __shfl_xor_sync(FULL, a0[i], 16);
    }
    const float inv = g_invdeg[node];
    float4 vv = __ldg(&v[node * 32 + c * 2 + pair]);
    const int k0 = pair * 4;
    float r0 = fmaxf(a0[k0 + 0] * inv + vv.x, 0.f);
    float r1 = fmaxf(a0[k0 + 1] * inv + vv.y, 0.f);
    float r2 = fmaxf(a0[k0 + 2] * inv + vv.z, 0.f);
    float r3 = fmaxf(a0[k0 + 3] * inv + vv.w, 0.f);
    hh[node * 32 + c * 2 + pair] = make_uint2(packh2(r0, r1), packh2(r2, r3));
}

// ---------------- fused: out = log_softmax(mean_agg(z_fp16) + pre) ----------
__global__ void k_agg64out(const uint4* __restrict__ z, const float4* __restrict__ pre,
                           float4* __restrict__ out, int n)
{
    int node = blockIdx.x * (blockDim.x >> 5) + (threadIdx.x >> 5);
    if (node >= n) return;
    const int lane = threadIdx.x & 31;
    const int quad = lane >> 3, c = lane & 7;
    const int beg = g_rowstart[node];
    const int cnt = g_rowstart[node + 1] - beg;

    float a0[8] = {0,0,0,0,0,0,0,0};
    float a1[8] = {0,0,0,0,0,0,0,0};

    for (int base = 0; base < cnt; base += 32) {
        const int m = min(32, cnt - base);
        int idx = (lane < m) ? __ldg(&g_srcs[beg + base + lane]) : 0;
        int j = 0;
        for (; j + 7 < m; j += 8) {
            int s0 = __shfl_sync(FULL, idx, j + quad);
            int s1 = __shfl_sync(FULL, idx, j + 4 + quad);
            uint4 w0 = __ldg(&z[s0 * 8 + c]);
            uint4 w1 = __ldg(&z[s1 * 8 + c]);
            acc8(a0, w0);
            acc8(a1, w1);
        }
        for (; j < m; j += 4) {
            int s0 = __shfl_sync(FULL, idx, (j + quad) & 31);
            if (j + quad < m) {
                uint4 w0 = __ldg(&z[s0 * 8 + c]);
                acc8(a0, w0);
            }
        }
    }
#pragma unroll
    for (int i = 0; i < 8; i++) {
        a0[i] += a1[i];
        a0[i] += __shfl_xor_sync(FULL, a0[i], 8);
        a0[i] += __shfl_xor_sync(FULL, a0[i], 16);
    }
    const float inv = g_invdeg[node];
    float4 p0 = __ldg(&pre[node * 16 + c * 2]);
    float4 p1 = __ldg(&pre[node * 16 + c * 2 + 1]);
    float vv[8];
    vv[0] = a0[0] * inv + p0.x; vv[1] = a0[1] * inv + p0.y;
    vv[2] = a0[2] * inv + p0.z; vv[3] = a0[3] * inv + p0.w;
    vv[4] = a0[4] * inv + p1.x; vv[5] = a0[5] * inv + p1.y;
    vv[6] = a0[6] * inv + p1.z; vv[7] = a0[7] * inv + p1.w;

    float m8 = vv[0];
#pragma unroll
    for (int i = 1; i < 8; i++) m8 = fmaxf(m8, vv[i]);
#pragma unroll
    for (int off = 4; off > 0; off >>= 1) m8 = fmaxf(m8, __shfl_xor_sync(FULL, m8, off));
    float s = 0.f;
#pragma unroll
    for (int i = 0; i < 8; i++) s += expf(vv[i] - m8);
#pragma unroll
    for (int off = 4; off > 0; off >>= 1) s += __shfl_xor_sync(FULL, s, off);
    float lse = m8 + logf(s);

    if (quad < 2) {
        const int k0 = quad * 4;
        out[node * 16 + c * 2 + quad] =
            make_float4(vv[k0 + 0] - lse, vv[k0 + 1] - lse,
                        vv[k0 + 2] - lse, vv[k0 + 3] - lse);
    }
}

// ---------------- launch -----------------------------------------------------
extern "C" void kernel_launch(void* const* d_in, const int* in_sizes, int n_in,
                              void* d_out, int out_size)
{
    const float* x   = (const float*)d_in[0];
    const int*   ei  = (const int*)d_in[1];
    const float* Wl1 = (const float*)d_in[2];
    const float* Wr1 = (const float*)d_in[3];
    const float* b1  = (const float*)d_in[4];
    const float* Wl2 = (const float*)d_in[5];
    const float* Wr2 = (const float*)d_in[6];
    const float* b2  = (const float*)d_in[7];
    float* out = (float*)d_out;

    const int n = in_sizes[0] / 128;
    const int e = in_sizes[1] / 2;
    const int* src = ei;
    const int* dst = ei + e;
    const int ntiles = (n + 127) / 128;

    static bool attr_done = false;
    if (!attr_done) {
        cudaFuncSetAttribute(mma_xproj, cudaFuncAttributeMaxDynamicSharedMemorySize, XP_SMEM);
        cudaFuncSetAttribute(mma_zp,    cudaFuncAttributeMaxDynamicSharedMemorySize, ZP_SMEM);
        attr_done = true;
    }

    void *p_u = nullptr, *p_v = nullptr, *p_hh = nullptr, *p_z = nullptr, *p_pre = nullptr;
    cudaGetSymbolAddress(&p_u, g_u);
    cudaGetSymbolAddress(&p_v, g_v);
    cudaGetSymbolAddress(&p_hh, g_hh);
    cudaGetSymbolAddress(&p_z, g_z);
    cudaGetSymbolAddress(&p_pre, g_pre);

    const int B = (n + 2047) / 2048;

    k_zero<<<(n + 1023) / 1024, 1024>>>(n);
    k_hist<<<(e + 255) / 256, 256>>>(dst, e);
    k_scanfill<<<B, 512>>>(n, e);
    k_cvtw<<<192, 256>>>(Wl1, Wr1, Wl2, Wr2);
    mma_xproj<<<ntiles, 256, XP_SMEM>>>(x, b1, (uint32_t*)p_u, (float2*)p_v, n);
    k_scatter<<<(e + 255) / 256, 256>>>(src, dst, e);
    k_aggrelu<<<(n + 7) / 8, 256>>>((const uint4*)p_u, (const float4*)p_v,
                                    (uint2*)p_hh, n);
    mma_zp<<<ntiles, 256, ZP_SMEM>>>(b2, (uint32_t*)p_z, (float2*)p_pre, n);
    k_agg64out<<<(n + 7) / 8, 256>>>((const uint4*)p_z, (const float4*)p_pre,
                                     (float4*)out, n);
}

// round 12
// speedup vs baseline: 2.1971x; 1.3379x over previous
#include <cuda_runtime.h>
#include <cuda_fp16.h>
#include <stdint.h>
#include <math.h>

#define NMAX 100000
#define EMAX 1600000
#define FULL 0xffffffffu

// ---------------- scratch (static device globals; no allocations) ----------
__device__ int   g_count[NMAX];
__device__ int   g_rowstart[NMAX + 1];
__device__ int   g_cursor[NMAX];
__device__ int   g_srcs[EMAX];
__device__ float g_invdeg[NMAX];
__device__ int   g_bflag[64];
__device__ int   g_bincl[64];
__device__ uint4 g_u[NMAX * 16];     // x @ Wl1, fp16 packed (128 halves/row)
__device__ float g_v[NMAX * 128];    // x @ Wr1 + b1 (fp32)
__device__ uint2 g_hh[NMAX * 32];    // hidden features, fp16 packed (128/row)
__device__ uint4 g_z[NMAX * 8];      // h @ Wl2, fp16 packed (64 halves/row)
__device__ float g_pre[NMAX * 64];   // h @ Wr2 + b2 (fp32)
__device__ uint4 g_w1h[256 * 16];    // [Wl1|Wr1]^T fp16: [n=256][k=128]
__device__ uint4 g_w2h[128 * 16];    // [Wl2|Wr2]^T fp16: [n=128][k=128]

// ---------------- helpers ---------------------------------------------------
__device__ __forceinline__ uint32_t smem_u32(const void* p) {
    uint32_t a;
    asm("{ .reg .u64 t; cvta.to.shared.u64 t, %1; cvt.u32.u64 %0, t; }" : "=r"(a) : "l"(p));
    return a;
}
__device__ __forceinline__ unsigned int packh2(float a, float b) {
    __half2 h = __floats2half2_rn(a, b);
    return *(unsigned int*)&h;
}
__device__ __forceinline__ void acc8(float* a, uint4 w) {
    float2 f0 = __half22float2(*(__half2*)&w.x);
    float2 f1 = __half22float2(*(__half2*)&w.y);
    float2 f2 = __half22float2(*(__half2*)&w.z);
    float2 f3 = __half22float2(*(__half2*)&w.w);
    a[0] += f0.x; a[1] += f0.y; a[2] += f1.x; a[3] += f1.y;
    a[4] += f2.x; a[5] += f2.y; a[6] += f3.x; a[7] += f3.y;
}

#define LDSM4(r, addr)                                                                \
    asm volatile("ldmatrix.sync.aligned.m8n8.x4.shared.b16 {%0,%1,%2,%3}, [%4];"      \
        : "=r"((r)[0]), "=r"((r)[1]), "=r"((r)[2]), "=r"((r)[3]) : "r"(addr))

#define MMA16816(d, a, b0, b1)                                                        \
    asm volatile("mma.sync.aligned.m16n8k16.row.col.f32.f16.f16.f32 "                 \
        "{%0,%1,%2,%3}, {%4,%5,%6,%7}, {%8,%9}, {%0,%1,%2,%3};"                       \
        : "+f"((d)[0]), "+f"((d)[1]), "+f"((d)[2]), "+f"((d)[3])                      \
        : "r"((a)[0]), "r"((a)[1]), "r"((a)[2]), "r"((a)[3]), "r"(b0), "r"(b1))

// ---------------- fused: histogram + weight convert -------------------------
// blocks [0, hb): histogram of dst; blocks [hb, hb+192): weight fp16 transpose
__global__ void k_histcvt(const int* __restrict__ dst, int e, int hb,
                          const float* __restrict__ Wl1, const float* __restrict__ Wr1,
                          const float* __restrict__ Wl2, const float* __restrict__ Wr2)
{
    const int bid = blockIdx.x;
    if (bid < hb) {
        int i = bid * 256 + threadIdx.x;
        if (i < e) atomicAdd(&g_count[dst[i]], 1);
    } else {
        int i = (bid - hb) * 256 + threadIdx.x;
        __half* w1 = (__half*)g_w1h;
        __half* w2 = (__half*)g_w2h;
        if (i < 256 * 128) {
            int nn = i >> 7, k = i & 127;
            float v = (nn < 128) ? Wl1[k * 128 + nn] : Wr1[k * 128 + (nn - 128)];
            w1[i] = __float2half_rn(v);
        } else if (i < 256 * 128 + 128 * 128) {
            int j = i - 256 * 128;
            int nn = j >> 7, k = j & 127;
            float v = (nn < 64) ? Wl2[k * 64 + nn] : Wr2[k * 64 + (nn - 64)];
            w2[j] = __float2half_rn(v);
        }
    }
}

__global__ void k_scanfill(int n, int e) {
    const int tid = threadIdx.x;
    const int lane = tid & 31, wid = tid >> 5;
    const int b = blockIdx.x;
    const int gbase = b * 2048 + tid * 4;
    int c[4];
    int s = 0;
#pragma unroll
    for (int j = 0; j < 4; j++) {
        c[j] = (gbase + j < n) ? g_count[gbase + j] : 0;
        s += c[j];
    }
    int incl = s;
#pragma unroll
    for (int off = 1; off < 32; off <<= 1) {
        int t = __shfl_up_sync(FULL, incl, off);
        if (lane >= off) incl += t;
    }
    __shared__ int wsum[16];
    __shared__ int sprev;
    if (lane == 31) wsum[wid] = incl;
    __syncthreads();
    if (tid < 16) {
        int v = wsum[tid];
#pragma unroll
        for (int off = 1; off < 16; off <<= 1) {
            int t = __shfl_up_sync(0xffffu, v, off);
            if (tid >= off) v += t;
        }
        wsum[tid] = v;
    }
    __syncthreads();
    if (tid == 0) {
        int prev = 0;
        if (b > 0) {
            while (atomicAdd(&g_bflag[b - 1], 0) == 0) {}
            prev = atomicAdd(&g_bincl[b - 1], 0);
        }
        g_bincl[b] = prev + wsum[15];
        __threadfence();
        atomicExch(&g_bflag[b], 1);
        sprev = prev;
        if (b == 0) g_rowstart[n] = e;
    }
    __syncthreads();
    int base = sprev + (incl - s) + (wid ? wsum[wid - 1] : 0);
#pragma unroll
    for (int j = 0; j < 4; j++) {
        if (gbase + j < n) {
            g_rowstart[gbase + j] = base;
            g_cursor[gbase + j] = base;
            g_invdeg[gbase + j] = 1.0f / fmaxf((float)c[j], 1.0f);
            base += c[j];
        }
    }
}

// ---------------- fused: scatter + mma.sync GEMM 1 --------------------------
// blocks [0, ntiles): [u|v] = x @ [Wl1|Wr1] tile; blocks [ntiles, +SCAT): CSR scatter.
// GEMM: CTA tile M=128, N=256, K=128; 8 warps = 4(m) x 2(n).
// smem: A[128][136] halves (34816B) + WT[256][136] halves (69632B) = 104448B.
#define SCAT_BLOCKS 1024
#define XP_SMEM (34816 + 69632)
__global__ __launch_bounds__(256, 2)
void k_scatxproj(const float* __restrict__ x, const float* __restrict__ bias,
                 uint32_t* __restrict__ u32, float2* __restrict__ v2, int n,
                 const int* __restrict__ src, const int* __restrict__ dst,
                 int e, int ntiles)
{
    extern __shared__ char smem[];
    const int tid = threadIdx.x;

    if ((int)blockIdx.x >= ntiles) {
        // ---- scatter part (no smem use) ----
        const int sb = blockIdx.x - ntiles;
        for (int i = sb * 256 + tid; i < e; i += SCAT_BLOCKS * 256) {
            int pos = atomicAdd(&g_cursor[dst[i]], 1);
            g_srcs[pos] = src[i];
        }
        return;
    }

    // ---- GEMM part ----
    const uint32_t sbA = smem_u32(smem);
    const uint32_t sbB = sbA + 34816;
    const int wid = tid >> 5, lane = tid & 31;
    const int row0T = blockIdx.x * 128;

    {
        const uint4* wt = (const uint4*)g_w1h;
        uint4* sB4 = (uint4*)(smem + 34816);
        for (int i = tid; i < 4096; i += 256) {
            int r = i >> 4, hc = i & 15;
            sB4[r * 17 + hc] = __ldg(&wt[r * 16 + hc]);
        }
    }
    {
        uint4* sA4 = (uint4*)smem;
        const float4* x4 = (const float4*)x;
        for (int i = tid; i < 2048; i += 256) {
            int r = i >> 4, hc = i & 15;
            int gr = row0T + r;
            uint4 val = make_uint4(0, 0, 0, 0);
            if (gr < n) {
                float4 f0 = __ldg(&x4[gr * 32 + hc * 2]);
                float4 f1 = __ldg(&x4[gr * 32 + hc * 2 + 1]);
                val = make_uint4(packh2(f0.x, f0.y), packh2(f0.z, f0.w),
                                 packh2(f1.x, f1.y), packh2(f1.z, f1.w));
            }
            sA4[r * 17 + hc] = val;
        }
    }
    __syncthreads();

    const int wm = wid & 3, gq = wid >> 2;
    const int gid = lane >> 2, tig = lane & 3;

    float acc[2][16][4];
#pragma unroll
    for (int mt = 0; mt < 2; mt++)
#pragma unroll
        for (int nt = 0; nt < 16; nt++)
#pragma unroll
            for (int q = 0; q < 4; q++) acc[mt][nt][q] = 0.f;

    const uint32_t aRow = (uint32_t)(wm * 32 + (lane & 15));
    const uint32_t aColOff = 8u * (lane >> 4);
    const uint32_t bRow = (uint32_t)(gq * 128 + (lane & 7) + 8 * (lane >> 4));
    const uint32_t bColOff = 8u * ((lane >> 3) & 1);

#pragma unroll
    for (int k0 = 0; k0 < 8; k0++) {
        const uint32_t kk = (uint32_t)k0 * 16;
        uint32_t a[2][4];
#pragma unroll
        for (int mt = 0; mt < 2; mt++) {
            uint32_t addr = sbA + ((aRow + mt * 16) * 136 + kk + aColOff) * 2;
            LDSM4(a[mt], addr);
        }
#pragma unroll
        for (int np = 0; np < 8; np++) {
            uint32_t addr = sbB + ((bRow + np * 16) * 136 + kk + bColOff) * 2;
            uint32_t b[4];
            LDSM4(b, addr);
#pragma unroll
            for (int mt = 0; mt < 2; mt++) {
                MMA16816(acc[mt][np * 2],     a[mt], b[0], b[1]);
                MMA16816(acc[mt][np * 2 + 1], a[mt], b[2], b[3]);
            }
        }
    }

#pragma unroll
    for (int mt = 0; mt < 2; mt++) {
        int r0 = row0T + wm * 32 + mt * 16 + gid;
        int r1 = r0 + 8;
        if (gq == 0) {
#pragma unroll
            for (int nt = 0; nt < 16; nt++) {
                if (r0 < n) u32[r0 * 64 + nt * 4 + tig] = packh2(acc[mt][nt][0], acc[mt][nt][1]);
                if (r1 < n) u32[r1 * 64 + nt * 4 + tig] = packh2(acc[mt][nt][2], acc[mt][nt][3]);
            }
        } else {
            const float2* b2 = (const float2*)bias;
#pragma unroll
            for (int nt = 0; nt < 16; nt++) {
                float2 bb = __ldg(&b2[nt * 4 + tig]);
                if (r0 < n) v2[r0 * 64 + nt * 4 + tig] =
                    make_float2(acc[mt][nt][0] + bb.x, acc[mt][nt][1] + bb.y);
                if (r1 < n) v2[r1 * 64 + nt * 4 + tig] =
                    make_float2(acc[mt][nt][2] + bb.x, acc[mt][nt][3] + bb.y);
            }
        }
    }
}

// ---------------- mma.sync GEMM 2: [z | pre] = h @ [Wl2 | Wr2] --------------
#define ZP_SMEM (34816 + 34816)
__global__ __launch_bounds__(256, 2)
void mma_zp(const float* __restrict__ bias,
            uint32_t* __restrict__ z32, float2* __restrict__ pre2, int n)
{
    extern __shared__ char smem[];
    const uint32_t sbA = smem_u32(smem);
    const uint32_t sbB = sbA + 34816;
    const int tid = threadIdx.x, wid = tid >> 5, lane = tid & 31;
    const int row0T = blockIdx.x * 128;

    {
        const uint4* wt = (const uint4*)g_w2h;
        uint4* sB4 = (uint4*)(smem + 34816);
        for (int i = tid; i < 2048; i += 256) {
            int r = i >> 4, hc = i & 15;
            sB4[r * 17 + hc] = __ldg(&wt[r * 16 + hc]);
        }
    }
    {
        uint4* sA4 = (uint4*)smem;
        const uint4* h16 = (const uint4*)g_hh;
        for (int i = tid; i < 2048; i += 256) {
            int r = i >> 4, hc = i & 15;
            int gr = row0T + r;
            uint4 val = make_uint4(0, 0, 0, 0);
            if (gr < n) val = __ldg(&h16[gr * 16 + hc]);
            sA4[r * 17 + hc] = val;
        }
    }
    __syncthreads();

    const int wm = wid & 3, gq = wid >> 2;
    const int gid = lane >> 2, tig = lane & 3;

    float acc[2][8][4];
#pragma unroll
    for (int mt = 0; mt < 2; mt++)
#pragma unroll
        for (int nt = 0; nt < 8; nt++)
#pragma unroll
            for (int q = 0; q < 4; q++) acc[mt][nt][q] = 0.f;

    const uint32_t aRow = (uint32_t)(wm * 32 + (lane & 15));
    const uint32_t aColOff = 8u * (lane >> 4);
    const uint32_t bRow = (uint32_t)(gq * 64 + (lane & 7) + 8 * (lane >> 4));
    const uint32_t bColOff = 8u * ((lane >> 3) & 1);

#pragma unroll
    for (int k0 = 0; k0 < 8; k0++) {
        const uint32_t kk = (uint32_t)k0 * 16;
        uint32_t a[2][4];
#pragma unroll
        for (int mt = 0; mt < 2; mt++) {
            uint32_t addr = sbA + ((aRow + mt * 16) * 136 + kk + aColOff) * 2;
            LDSM4(a[mt], addr);
        }
#pragma unroll
        for (int np = 0; np < 4; np++) {
            uint32_t addr = sbB + ((bRow + np * 16) * 136 + kk + bColOff) * 2;
            uint32_t b[4];
            LDSM4(b, addr);
#pragma unroll
            for (int mt = 0; mt < 2; mt++) {
                MMA16816(acc[mt][np * 2],     a[mt], b[0], b[1]);
                MMA16816(acc[mt][np * 2 + 1], a[mt], b[2], b[3]);
            }
        }
    }

#pragma unroll
    for (int mt = 0; mt < 2; mt++) {
        int r0 = row0T + wm * 32 + mt * 16 + gid;
        int r1 = r0 + 8;
        if (gq == 0) {
#pragma unroll
            for (int nt = 0; nt < 8; nt++) {
                if (r0 < n) z32[r0 * 32 + nt * 4 + tig] = packh2(acc[mt][nt][0], acc[mt][nt][1]);
                if (r1 < n) z32[r1 * 32 + nt * 4 + tig] = packh2(acc[mt][nt][2], acc[mt][nt][3]);
            }
        } else {
            const float2* b2 = (const float2*)bias;
#pragma unroll
            for (int nt = 0; nt < 8; nt++) {
                float2 bb = __ldg(&b2[nt * 4 + tig]);
                if (r0 < n) pre2[r0 * 32 + nt * 4 + tig] =
                    make_float2(acc[mt][nt][0] + bb.x, acc[mt][nt][1] + bb.y);
                if (r1 < n) pre2[r1 * 32 + nt * 4 + tig] =
                    make_float2(acc[mt][nt][2] + bb.x, acc[mt][nt][3] + bb.y);
            }
        }
    }
}

// ---------------- fused: h = fp16(relu(mean_agg(u_fp16) + v)) ---------------
__global__ void k_aggrelu(const uint4* __restrict__ u, const float4* __restrict__ v,
                          uint2* __restrict__ hh, int n)
{
    int node = blockIdx.x * (blockDim.x >> 5) + (threadIdx.x >> 5);
    if (node >= n) return;
    const int lane = threadIdx.x & 31;
    const int pair = lane >> 4, c = lane & 15;
    const int beg = g_rowstart[node];
    const int cnt = g_rowstart[node + 1] - beg;

    float a0[8] = {0,0,0,0,0,0,0,0};
    float a1[8] = {0,0,0,0,0,0,0,0};

    for (int base = 0; base < cnt; base += 32) {
        const int m = min(32, cnt - base);
        int idx = (lane < m) ? __ldg(&g_srcs[beg + base + lane]) : 0;
        int j = 0;
        for (; j + 3 < m; j += 4) {
            int s0 = __shfl_sync(FULL, idx, j + pair);
            int s1 = __shfl_sync(FULL, idx, j + 2 + pair);
            uint4 w0 = __ldg(&u[s0 * 16 + c]);
            uint4 w1 = __ldg(&u[s1 * 16 + c]);
            acc8(a0, w0);
            acc8(a1, w1);
        }
        for (; j < m; j += 2) {
            int s0 = __shfl_sync(FULL, idx, (j + pair) & 31);
            if (j + pair < m) {
                uint4 w0 = __ldg(&u[s0 * 16 + c]);
                acc8(a0, w0);
            }
        }
    }
#pragma unroll
    for (int i = 0; i < 8; i++) {
        a0[i] += a1[i];
        a0[i] += __shfl_xor_sync(FULL, a0[i], 16);
    }
    const float inv = g_invdeg[node];
    float4 vv = __ldg(&v[node * 32 + c * 2 + pair]);
    const int k0 = pair * 4;
    float r0 = fmaxf(a0[k0 + 0] * inv + vv.x, 0.f);
    float r1 = fmaxf(a0[k0 + 1] * inv + vv.y, 0.f);
    float r2 = fmaxf(a0[k0 + 2] * inv + vv.z, 0.f);
    float r3 = fmaxf(a0[k0 + 3] * inv + vv.w, 0.f);
    hh[node * 32 + c * 2 + pair] = make_uint2(packh2(r0, r1), packh2(r2, r3));
}

// ---------------- fused: out = log_softmax(mean_agg(z_fp16) + pre) ----------
__global__ void k_agg64out(const uint4* __restrict__ z, const float4* __restrict__ pre,
                           float4* __restrict__ out, int n)
{
    int node = blockIdx.x * (blockDim.x >> 5) + (threadIdx.x >> 5);
    if (node >= n) return;
    const int lane = threadIdx.x & 31;
    const int quad = lane >> 3, c = lane & 7;
    const int beg = g_rowstart[node];
    const int cnt = g_rowstart[node + 1] - beg;

    float a0[8] = {0,0,0,0,0,0,0,0};
    float a1[8] = {0,0,0,0,0,0,0,0};

    for (int base = 0; base < cnt; base += 32) {
        const int m = min(32, cnt - base);
        int idx = (lane < m) ? __ldg(&g_srcs[beg + base + lane]) : 0;
        int j = 0;
        for (; j + 7 < m; j += 8) {
            int s0 = __shfl_sync(FULL, idx, j + quad);
            int s1 = __shfl_sync(FULL, idx, j + 4 + quad);
            uint4 w0 = __ldg(&z[s0 * 8 + c]);
            uint4 w1 = __ldg(&z[s1 * 8 + c]);
            acc8(a0, w0);
            acc8(a1, w1);
        }
        for (; j < m; j += 4) {
            int s0 = __shfl_sync(FULL, idx, (j + quad) & 31);
            if (j + quad < m) {
                uint4 w0 = __ldg(&z[s0 * 8 + c]);
                acc8(a0, w0);
            }
        }
    }
#pragma unroll
    for (int i = 0; i < 8; i++) {
        a0[i] += a1[i];
        a0[i] += __shfl_xor_sync(FULL, a0[i], 8);
        a0[i] += __shfl_xor_sync(FULL, a0[i], 16);
    }
    const float inv = g_invdeg[node];
    float4 p0 = __ldg(&pre[node * 16 + c * 2]);
    float4 p1 = __ldg(&pre[node * 16 + c * 2 + 1]);
    float vv[8];
    vv[0] = a0[0] * inv + p0.x; vv[1] = a0[1] * inv + p0.y;
    vv[2] = a0[2] * inv + p0.z; vv[3] = a0[3] * inv + p0.w;
    vv[4] = a0[4] * inv + p1.x; vv[5] = a0[5] * inv + p1.y;
    vv[6] = a0[6] * inv + p1.z; vv[7] = a0[7] * inv + p1.w;

    float m8 = vv[0];
#pragma unroll
    for (int i = 1; i < 8; i++) m8 = fmaxf(m8, vv[i]);
#pragma unroll
    for (int off = 4; off > 0; off >>= 1) m8 = fmaxf(m8, __shfl_xor_sync(FULL, m8, off));
    float s = 0.f;
#pragma unroll
    for (int i = 0; i < 8; i++) s += expf(vv[i] - m8);
#pragma unroll
    for (int off = 4; off > 0; off >>= 1) s += __shfl_xor_sync(FULL, s, off);
    float lse = m8 + logf(s);

    if (quad < 2) {
        const int k0 = quad * 4;
        out[node * 16 + c * 2 + quad] =
            make_float4(vv[k0 + 0] - lse, vv[k0 + 1] - lse,
                        vv[k0 + 2] - lse, vv[k0 + 3] - lse);
    }
}

// ---------------- launch -----------------------------------------------------
extern "C" void kernel_launch(void* const* d_in, const int* in_sizes, int n_in,
                              void* d_out, int out_size)
{
    const float* x   = (const float*)d_in[0];
    const int*   ei  = (const int*)d_in[1];
    const float* Wl1 = (const float*)d_in[2];
    const float* Wr1 = (const float*)d_in[3];
    const float* b1  = (const float*)d_in[4];
    const float* Wl2 = (const float*)d_in[5];
    const float* Wr2 = (const float*)d_in[6];
    const float* b2  = (const float*)d_in[7];
    float* out = (float*)d_out;

    const int n = in_sizes[0] / 128;
    const int e = in_sizes[1] / 2;
    const int* src = ei;
    const int* dst = ei + e;
    const int ntiles = (n + 127) / 128;

    static bool attr_done = false;
    if (!attr_done) {
        cudaFuncSetAttribute(k_scatxproj, cudaFuncAttributeMaxDynamicSharedMemorySize, XP_SMEM);
        cudaFuncSetAttribute(mma_zp,      cudaFuncAttributeMaxDynamicSharedMemorySize, ZP_SMEM);
        attr_done = true;
    }

    void *p_cnt = nullptr, *p_flag = nullptr;
    void *p_u = nullptr, *p_v = nullptr, *p_hh = nullptr, *p_z = nullptr, *p_pre = nullptr;
    cudaGetSymbolAddress(&p_cnt, g_count);
    cudaGetSymbolAddress(&p_flag, g_bflag);
    cudaGetSymbolAddress(&p_u, g_u);
    cudaGetSymbolAddress(&p_v, g_v);
    cudaGetSymbolAddress(&p_hh, g_hh);
    cudaGetSymbolAddress(&p_z, g_z);
    cudaGetSymbolAddress(&p_pre, g_pre);

    const int B = (n + 2047) / 2048;
    const int hb = (e + 255) / 256;

    cudaMemsetAsync(p_cnt, 0, (size_t)n * sizeof(int));
    cudaMemsetAsync(p_flag, 0, 64 * sizeof(int));

    // launch 1: histogram + weight convert (independent, fused)
    k_histcvt<<<hb + 192, 256>>>(dst, e, hb, Wl1, Wr1, Wl2, Wr2);
    // launch 2: scan + fill
    k_scanfill<<<B, 512>>>(n, e);
    // launch 3: scatter + x-projection GEMM (independent, fused)
    k_scatxproj<<<ntiles + SCAT_BLOCKS, 256, XP_SMEM>>>(
        x, b1, (uint32_t*)p_u, (float2*)p_v, n, src, dst, e, ntiles);
    // launch 4 (ncu-captured): fused aggregation + relu
    k_aggrelu<<<(n + 7) / 8, 256>>>((const uint4*)p_u, (const float4*)p_v,
                                    (uint2*)p_hh, n);
    // launch 5: layer-2 projections
    mma_zp<<<ntiles, 256, ZP_SMEM>>>(b2, (uint32_t*)p_z, (float2*)p_pre, n);
    // launch 6: fused aggregation + log_softmax
    k_agg64out<<<(n + 7) / 8, 256>>>((const uint4*)p_z, (const float4*)p_pre,
                                     (float4*)out, n);
}

// round 13
// speedup vs baseline: 2.4561x; 1.1179x over previous
#include <cuda_runtime.h>
#include <cuda_fp16.h>
#include <stdint.h>
#include <math.h>

#define NMAX 100000
#define EMAX 1600000
#define FULL 0xffffffffu

// ---------------- scratch (static device globals; no allocations) ----------
__device__ int      g_count[NMAX];
__device__ int      g_rowstart[NMAX + 1];
__device__ int      g_cursor[NMAX];
__device__ int      g_srcs[EMAX];
__device__ float    g_invdeg[NMAX];
__device__ int      g_bflag[64];
__device__ int      g_bincl[64];
__device__ uint4    g_u[NMAX * 16];    // x @ Wl1, fp16 (128 halves/row)
__device__ uint32_t g_v[NMAX * 64];    // x @ Wr1 + b1, fp16 (128 halves/row)
__device__ uint2    g_hh[NMAX * 32];   // hidden, fp16 (128 halves/row)
__device__ uint4    g_z[NMAX * 8];     // h @ Wl2, fp16 (64 halves/row)
__device__ uint32_t g_pre[NMAX * 32];  // h @ Wr2 + b2, fp16 (64 halves/row)
__device__ uint4    g_w1h[256 * 16];   // [Wl1|Wr1]^T fp16: [n=256][k=128]
__device__ uint4    g_w2h[128 * 16];   // [Wl2|Wr2]^T fp16: [n=128][k=128]

// ---------------- helpers ---------------------------------------------------
__device__ __forceinline__ uint32_t smem_u32(const void* p) {
    uint32_t a;
    asm("{ .reg .u64 t; cvta.to.shared.u64 t, %1; cvt.u32.u64 %0, t; }" : "=r"(a) : "l"(p));
    return a;
}
__device__ __forceinline__ unsigned int packh2(float a, float b) {
    __half2 h = __floats2half2_rn(a, b);
    return *(unsigned int*)&h;
}
// accumulate one fp16x8 row
__device__ __forceinline__ void acc8(float* a, uint4 w) {
    float2 f0 = __half22float2(*(__half2*)&w.x);
    float2 f1 = __half22float2(*(__half2*)&w.y);
    float2 f2 = __half22float2(*(__half2*)&w.z);
    float2 f3 = __half22float2(*(__half2*)&w.w);
    a[0] += f0.x; a[1] += f0.y; a[2] += f1.x; a[3] += f1.y;
    a[4] += f2.x; a[5] += f2.y; a[6] += f3.x; a[7] += f3.y;
}
// pairwise fp16 add of two rows, then fp32 accumulate (20 ops vs 32)
__device__ __forceinline__ void accpair(float* a, uint4 w0, uint4 w1) {
    __half2 s0 = __hadd2(*(__half2*)&w0.x, *(__half2*)&w1.x);
    __half2 s1 = __hadd2(*(__half2*)&w0.y, *(__half2*)&w1.y);
    __half2 s2 = __hadd2(*(__half2*)&w0.z, *(__half2*)&w1.z);
    __half2 s3 = __hadd2(*(__half2*)&w0.w, *(__half2*)&w1.w);
    float2 f0 = __half22float2(s0);
    float2 f1 = __half22float2(s1);
    float2 f2 = __half22float2(s2);
    float2 f3 = __half22float2(s3);
    a[0] += f0.x; a[1] += f0.y; a[2] += f1.x; a[3] += f1.y;
    a[4] += f2.x; a[5] += f2.y; a[6] += f3.x; a[7] += f3.y;
}

#define LDSM4(r, addr)                                                                \
    asm volatile("ldmatrix.sync.aligned.m8n8.x4.shared.b16 {%0,%1,%2,%3}, [%4];"      \
        : "=r"((r)[0]), "=r"((r)[1]), "=r"((r)[2]), "=r"((r)[3]) : "r"(addr))

#define MMA16816(d, a, b0, b1)                                                        \
    asm volatile("mma.sync.aligned.m16n8k16.row.col.f32.f16.f16.f32 "                 \
        "{%0,%1,%2,%3}, {%4,%5,%6,%7}, {%8,%9}, {%0,%1,%2,%3};"                       \
        : "+f"((d)[0]), "+f"((d)[1]), "+f"((d)[2]), "+f"((d)[3])                      \
        : "r"((a)[0]), "r"((a)[1]), "r"((a)[2]), "r"((a)[3]), "r"(b0), "r"(b1))

// ---------------- CSR build -------------------------------------------------
__global__ void k_zero(int n) {
    int i = blockIdx.x * blockDim.x + threadIdx.x;
    if (i < n) g_count[i] = 0;
    if (i < 64) g_bflag[i] = 0;
}

// fused: histogram + weight convert
__global__ void k_histcvt(const int* __restrict__ dst, int e, int hb,
                          const float* __restrict__ Wl1, const float* __restrict__ Wr1,
                          const float* __restrict__ Wl2, const float* __restrict__ Wr2)
{
    const int bid = blockIdx.x;
    if (bid < hb) {
        int i = bid * 256 + threadIdx.x;
        if (i < e) atomicAdd(&g_count[dst[i]], 1);
    } else {
        int i = (bid - hb) * 256 + threadIdx.x;
        __half* w1 = (__half*)g_w1h;
        __half* w2 = (__half*)g_w2h;
        if (i < 256 * 128) {
            int nn = i >> 7, k = i & 127;
            float v = (nn < 128) ? Wl1[k * 128 + nn] : Wr1[k * 128 + (nn - 128)];
            w1[i] = __float2half_rn(v);
        } else if (i < 256 * 128 + 128 * 128) {
            int j = i - 256 * 128;
            int nn = j >> 7, k = j & 127;
            float v = (nn < 64) ? Wl2[k * 64 + nn] : Wr2[k * 64 + (nn - 64)];
            w2[j] = __float2half_rn(v);
        }
    }
}

__global__ void k_scanfill(int n, int e) {
    const int tid = threadIdx.x;
    const int lane = tid & 31, wid = tid >> 5;
    const int b = blockIdx.x;
    const int gbase = b * 2048 + tid * 4;
    int c[4];
    int s = 0;
#pragma unroll
    for (int j = 0; j < 4; j++) {
        c[j] = (gbase + j < n) ? g_count[gbase + j] : 0;
        s += c[j];
    }
    int incl = s;
#pragma unroll
    for (int off = 1; off < 32; off <<= 1) {
        int t = __shfl_up_sync(FULL, incl, off);
        if (lane >= off) incl += t;
    }
    __shared__ int wsum[16];
    __shared__ int sprev;
    if (lane == 31) wsum[wid] = incl;
    __syncthreads();
    if (tid < 16) {
        int v = wsum[tid];
#pragma unroll
        for (int off = 1; off < 16; off <<= 1) {
            int t = __shfl_up_sync(0xffffu, v, off);
            if (tid >= off) v += t;
        }
        wsum[tid] = v;
    }
    __syncthreads();
    if (tid == 0) {
        int prev = 0;
        if (b > 0) {
            while (atomicAdd(&g_bflag[b - 1], 0) == 0) {}
            prev = atomicAdd(&g_bincl[b - 1], 0);
        }
        g_bincl[b] = prev + wsum[15];
        __threadfence();
        atomicExch(&g_bflag[b], 1);
        sprev = prev;
        if (b == 0) g_rowstart[n] = e;
    }
    __syncthreads();
    int base = sprev + (incl - s) + (wid ? wsum[wid - 1] : 0);
#pragma unroll
    for (int j = 0; j < 4; j++) {
        if (gbase + j < n) {
            g_rowstart[gbase + j] = base;
            g_cursor[gbase + j] = base;
            g_invdeg[gbase + j] = 1.0f / fmaxf((float)c[j], 1.0f);
            base += c[j];
        }
    }
}

// ---------------- fused: scatter + mma.sync GEMM 1 --------------------------
#define SCAT_BLOCKS 1024
#define XP_SMEM (34816 + 69632)
__global__ __launch_bounds__(256, 2)
void k_scatxproj(const float* __restrict__ x, const float* __restrict__ bias,
                 uint32_t* __restrict__ u32, uint32_t* __restrict__ v32, int n,
                 const int* __restrict__ src, const int* __restrict__ dst,
                 int e, int ntiles)
{
    extern __shared__ char smem[];
    const int tid = threadIdx.x;

    if ((int)blockIdx.x >= ntiles) {
        const int sb = blockIdx.x - ntiles;
        for (int i = sb * 256 + tid; i < e; i += SCAT_BLOCKS * 256) {
            int pos = atomicAdd(&g_cursor[dst[i]], 1);
            g_srcs[pos] = src[i];
        }
        return;
    }

    const uint32_t sbA = smem_u32(smem);
    const uint32_t sbB = sbA + 34816;
    const int wid = tid >> 5, lane = tid & 31;
    const int row0T = blockIdx.x * 128;

    {
        const uint4* wt = (const uint4*)g_w1h;
        uint4* sB4 = (uint4*)(smem + 34816);
        for (int i = tid; i < 4096; i += 256) {
            int r = i >> 4, hc = i & 15;
            sB4[r * 17 + hc] = __ldg(&wt[r * 16 + hc]);
        }
    }
    {
        uint4* sA4 = (uint4*)smem;
        const float4* x4 = (const float4*)x;
        for (int i = tid; i < 2048; i += 256) {
            int r = i >> 4, hc = i & 15;
            int gr = row0T + r;
            uint4 val = make_uint4(0, 0, 0, 0);
            if (gr < n) {
                float4 f0 = __ldg(&x4[gr * 32 + hc * 2]);
                float4 f1 = __ldg(&x4[gr * 32 + hc * 2 + 1]);
                val = make_uint4(packh2(f0.x, f0.y), packh2(f0.z, f0.w),
                                 packh2(f1.x, f1.y), packh2(f1.z, f1.w));
            }
            sA4[r * 17 + hc] = val;
        }
    }
    __syncthreads();

    const int wm = wid & 3, gq = wid >> 2;
    const int gid = lane >> 2, tig = lane & 3;

    float acc[2][16][4];
#pragma unroll
    for (int mt = 0; mt < 2; mt++)
#pragma unroll
        for (int nt = 0; nt < 16; nt++)
#pragma unroll
            for (int q = 0; q < 4; q++) acc[mt][nt][q] = 0.f;

    const uint32_t aRow = (uint32_t)(wm * 32 + (lane & 15));
    const uint32_t aColOff = 8u * (lane >> 4);
    const uint32_t bRow = (uint32_t)(gq * 128 + (lane & 7) + 8 * (lane >> 4));
    const uint32_t bColOff = 8u * ((lane >> 3) & 1);

#pragma unroll
    for (int k0 = 0; k0 < 8; k0++) {
        const uint32_t kk = (uint32_t)k0 * 16;
        uint32_t a[2][4];
#pragma unroll
        for (int mt = 0; mt < 2; mt++) {
            uint32_t addr = sbA + ((aRow + mt * 16) * 136 + kk + aColOff) * 2;
            LDSM4(a[mt], addr);
        }
#pragma unroll
        for (int np = 0; np < 8; np++) {
            uint32_t addr = sbB + ((bRow + np * 16) * 136 + kk + bColOff) * 2;
            uint32_t b[4];
            LDSM4(b, addr);
#pragma unroll
            for (int mt = 0; mt < 2; mt++) {
                MMA16816(acc[mt][np * 2],     a[mt], b[0], b[1]);
                MMA16816(acc[mt][np * 2 + 1], a[mt], b[2], b[3]);
            }
        }
    }

#pragma unroll
    for (int mt = 0; mt < 2; mt++) {
        int r0 = row0T + wm * 32 + mt * 16 + gid;
        int r1 = r0 + 8;
        if (gq == 0) {
#pragma unroll
            for (int nt = 0; nt < 16; nt++) {
                if (r0 < n) u32[r0 * 64 + nt * 4 + tig] = packh2(acc[mt][nt][0], acc[mt][nt][1]);
                if (r1 < n) u32[r1 * 64 + nt * 4 + tig] = packh2(acc[mt][nt][2], acc[mt][nt][3]);
            }
        } else {
            const float2* b2 = (const float2*)bias;
#pragma unroll
            for (int nt = 0; nt < 16; nt++) {
                float2 bb = __ldg(&b2[nt * 4 + tig]);
                if (r0 < n) v32[r0 * 64 + nt * 4 + tig] =
                    packh2(acc[mt][nt][0] + bb.x, acc[mt][nt][1] + bb.y);
                if (r1 < n) v32[r1 * 64 + nt * 4 + tig] =
                    packh2(acc[mt][nt][2] + bb.x, acc[mt][nt][3] + bb.y);
            }
        }
    }
}

// ---------------- mma.sync GEMM 2: [z | pre] = h @ [Wl2 | Wr2] --------------
#define ZP_SMEM (34816 + 34816)
__global__ __launch_bounds__(256, 2)
void mma_zp(const float* __restrict__ bias,
            uint32_t* __restrict__ z32, uint32_t* __restrict__ pre32, int n)
{
    extern __shared__ char smem[];
    const uint32_t sbA = smem_u32(smem);
    const uint32_t sbB = sbA + 34816;
    const int tid = threadIdx.x, wid = tid >> 5, lane = tid & 31;
    const int row0T = blockIdx.x * 128;

    {
        const uint4* wt = (const uint4*)g_w2h;
        uint4* sB4 = (uint4*)(smem + 34816);
        for (int i = tid; i < 2048; i += 256) {
            int r = i >> 4, hc = i & 15;
            sB4[r * 17 + hc] = __ldg(&wt[r * 16 + hc]);
        }
    }
    {
        uint4* sA4 = (uint4*)smem;
        const uint4* h16 = (const uint4*)g_hh;
        for (int i = tid; i < 2048; i += 256) {
            int r = i >> 4, hc = i & 15;
            int gr = row0T + r;
            uint4 val = make_uint4(0, 0, 0, 0);
            if (gr < n) val = __ldg(&h16[gr * 16 + hc]);
            sA4[r * 17 + hc] = val;
        }
    }
    __syncthreads();

    const int wm = wid & 3, gq = wid >> 2;
    const int gid = lane >> 2, tig = lane & 3;

    float acc[2][8][4];
#pragma unroll
    for (int mt = 0; mt < 2; mt++)
#pragma unroll
        for (int nt = 0; nt < 8; nt++)
#pragma unroll
            for (int q = 0; q < 4; q++) acc[mt][nt][q] = 0.f;

    const uint32_t aRow = (uint32_t)(wm * 32 + (lane & 15));
    const uint32_t aColOff = 8u * (lane >> 4);
    const uint32_t bRow = (uint32_t)(gq * 64 + (lane & 7) + 8 * (lane >> 4));
    const uint32_t bColOff = 8u * ((lane >> 3) & 1);

#pragma unroll
    for (int k0 = 0; k0 < 8; k0++) {
        const uint32_t kk = (uint32_t)k0 * 16;
        uint32_t a[2][4];
#pragma unroll
        for (int mt = 0; mt < 2; mt++) {
            uint32_t addr = sbA + ((aRow + mt * 16) * 136 + kk + aColOff) * 2;
            LDSM4(a[mt], addr);
        }
#pragma unroll
        for (int np = 0; np < 4; np++) {
            uint32_t addr = sbB + ((bRow + np * 16) * 136 + kk + bColOff) * 2;
            uint32_t b[4];
            LDSM4(b, addr);
#pragma unroll
            for (int mt = 0; mt < 2; mt++) {
                MMA16816(acc[mt][np * 2],     a[mt], b[0], b[1]);
                MMA16816(acc[mt][np * 2 + 1], a[mt], b[2], b[3]);
            }
        }
    }

#pragma unroll
    for (int mt = 0; mt < 2; mt++) {
        int r0 = row0T + wm * 32 + mt * 16 + gid;
        int r1 = r0 + 8;
        if (gq == 0) {
#pragma unroll
            for (int nt = 0; nt < 8; nt++) {
                if (r0 < n) z32[r0 * 32 + nt * 4 + tig] = packh2(acc[mt][nt][0], acc[mt][nt][1]);
                if (r1 < n) z32[r1 * 32 + nt * 4 + tig] = packh2(acc[mt][nt][2], acc[mt][nt][3]);
            }
        } else {
            const float2* b2 = (const float2*)bias;
#pragma unroll
            for (int nt = 0; nt < 8; nt++) {
                float2 bb = __ldg(&b2[nt * 4 + tig]);
                if (r0 < n) pre32[r0 * 32 + nt * 4 + tig] =
                    packh2(acc[mt][nt][0] + bb.x, acc[mt][nt][1] + bb.y);
                if (r1 < n) pre32[r1 * 32 + nt * 4 + tig] =
                    packh2(acc[mt][nt][2] + bb.x, acc[mt][nt][3] + bb.y);
            }
        }
    }
}

// ---------------- fused: h = fp16(relu(mean_agg(u_fp16) + v_fp16)) ----------
__global__ void k_aggrelu(const uint4* __restrict__ u, const uint2* __restrict__ v,
                          uint2* __restrict__ hh, int n)
{
    int node = blockIdx.x * (blockDim.x >> 5) + (threadIdx.x >> 5);
    if (node >= n) return;
    const int lane = threadIdx.x & 31;
    const int pair = lane >> 4, c = lane & 15;
    const int beg = g_rowstart[node];
    const int cnt = g_rowstart[node + 1] - beg;

    float a0[8] = {0,0,0,0,0,0,0,0};

    for (int base = 0; base < cnt; base += 32) {
        const int m = min(32, cnt - base);
        int idx = (lane < m) ? __ldg(&g_srcs[beg + base + lane]) : 0;
        int j = 0;
        for (; j + 3 < m; j += 4) {
            int s0 = __shfl_sync(FULL, idx, j + pair);
            int s1 = __shfl_sync(FULL, idx, j + 2 + pair);
            uint4 w0 = __ldg(&u[s0 * 16 + c]);
            uint4 w1 = __ldg(&u[s1 * 16 + c]);
            accpair(a0, w0, w1);
        }
        for (; j < m; j += 2) {
            int s0 = __shfl_sync(FULL, idx, (j + pair) & 31);
            if (j + pair < m) {
                uint4 w0 = __ldg(&u[s0 * 16 + c]);
                acc8(a0, w0);
            }
        }
    }
#pragma unroll
    for (int i = 0; i < 8; i++)
        a0[i] += __shfl_xor_sync(FULL, a0[i], 16);

    const float inv = g_invdeg[node];
    uint2 vv = __ldg(&v[node * 32 + c * 2 + pair]);
    float2 v0 = __half22float2(*(__half2*)&vv.x);
    float2 v1 = __half22float2(*(__half2*)&vv.y);
    const int k0 = pair * 4;
    float r0 = fmaxf(a0[k0 + 0] * inv + v0.x, 0.f);
    float r1 = fmaxf(a0[k0 + 1] * inv + v0.y, 0.f);
    float r2 = fmaxf(a0[k0 + 2] * inv + v1.x, 0.f);
    float r3 = fmaxf(a0[k0 + 3] * inv + v1.y, 0.f);
    hh[node * 32 + c * 2 + pair] = make_uint2(packh2(r0, r1), packh2(r2, r3));
}

// ---------------- fused: out = log_softmax(mean_agg(z_fp16) + pre_fp16) -----
__global__ void k_agg64out(const uint4* __restrict__ z, const uint4* __restrict__ pre,
                           float4* __restrict__ out, int n)
{
    int node = blockIdx.x * (blockDim.x >> 5) + (threadIdx.x >> 5);
    if (node >= n) return;
    const int lane = threadIdx.x & 31;
    const int quad = lane >> 3, c = lane & 7;
    const int beg = g_rowstart[node];
    const int cnt = g_rowstart[node + 1] - beg;

    float a0[8] = {0,0,0,0,0,0,0,0};

    for (int base = 0; base < cnt; base += 32) {
        const int m = min(32, cnt - base);
        int idx = (lane < m) ? __ldg(&g_srcs[beg + base + lane]) : 0;
        int j = 0;
        for (; j + 7 < m; j += 8) {
            int s0 = __shfl_sync(FULL, idx, j + quad);
            int s1 = __shfl_sync(FULL, idx, j + 4 + quad);
            uint4 w0 = __ldg(&z[s0 * 8 + c]);
            uint4 w1 = __ldg(&z[s1 * 8 + c]);
            accpair(a0, w0, w1);
        }
        for (; j < m; j += 4) {
            int s0 = __shfl_sync(FULL, idx, (j + quad) & 31);
            if (j + quad < m) {
                uint4 w0 = __ldg(&z[s0 * 8 + c]);
                acc8(a0, w0);
            }
        }
    }
#pragma unroll
    for (int i = 0; i < 8; i++) {
        a0[i] += __shfl_xor_sync(FULL, a0[i], 8);
        a0[i] += __shfl_xor_sync(FULL, a0[i], 16);
    }
    const float inv = g_invdeg[node];
    uint4 pp = __ldg(&pre[node * 8 + c]);
    float2 p0 = __half22float2(*(__half2*)&pp.x);
    float2 p1 = __half22float2(*(__half2*)&pp.y);
    float2 p2 = __half22float2(*(__half2*)&pp.z);
    float2 p3 = __half22float2(*(__half2*)&pp.w);
    float vv[8];
    vv[0] = a0[0] * inv + p0.x; vv[1] = a0[1] * inv + p0.y;
    vv[2] = a0[2] * inv + p1.x; vv[3] = a0[3] * inv + p1.y;
    vv[4] = a0[4] * inv + p2.x; vv[5] = a0[5] * inv + p2.y;
    vv[6] = a0[6] * inv + p3.x; vv[7] = a0[7] * inv + p3.y;

    float m8 = vv[0];
#pragma unroll
    for (int i = 1; i < 8; i++) m8 = fmaxf(m8, vv[i]);
#pragma unroll
    for (int off = 4; off > 0; off >>= 1) m8 = fmaxf(m8, __shfl_xor_sync(FULL, m8, off));
    float s = 0.f;
#pragma unroll
    for (int i = 0; i < 8; i++) s += expf(vv[i] - m8);
#pragma unroll
    for (int off = 4; off > 0; off >>= 1) s += __shfl_xor_sync(FULL, s, off);
    float lse = m8 + logf(s);

    if (quad < 2) {
        const int k0 = quad * 4;
        out[node * 16 + c * 2 + quad] =
            make_float4(vv[k0 + 0] - lse, vv[k0 + 1] - lse,
                        vv[k0 + 2] - lse, vv[k0 + 3] - lse);
    }
}

// ---------------- launch -----------------------------------------------------
extern "C" void kernel_launch(void* const* d_in, const int* in_sizes, int n_in,
                              void* d_out, int out_size)
{
    const float* x   = (const float*)d_in[0];
    const int*   ei  = (const int*)d_in[1];
    const float* Wl1 = (const float*)d_in[2];
    const float* Wr1 = (const float*)d_in[3];
    const float* b1  = (const float*)d_in[4];
    const float* Wl2 = (const float*)d_in[5];
    const float* Wr2 = (const float*)d_in[6];
    const float* b2  = (const float*)d_in[7];
    float* out = (float*)d_out;

    const int n = in_sizes[0] / 128;
    const int e = in_sizes[1] / 2;
    const int* src = ei;
    const int* dst = ei + e;
    const int ntiles = (n + 127) / 128;

    static bool attr_done = false;
    if (!attr_done) {
        cudaFuncSetAttribute(k_scatxproj, cudaFuncAttributeMaxDynamicSharedMemorySize, XP_SMEM);
        cudaFuncSetAttribute(mma_zp,      cudaFuncAttributeMaxDynamicSharedMemorySize, ZP_SMEM);
        attr_done = true;
    }

    void *p_u = nullptr, *p_v = nullptr, *p_hh = nullptr, *p_z = nullptr, *p_pre = nullptr;
    cudaGetSymbolAddress(&p_u, g_u);
    cudaGetSymbolAddress(&p_v, g_v);
    cudaGetSymbolAddress(&p_hh, g_hh);
    cudaGetSymbolAddress(&p_z, g_z);
    cudaGetSymbolAddress(&p_pre, g_pre);

    const int B = (n + 2047) / 2048;
    const int hb = (e + 255) / 256;

    // launch 1: zero counts + flags
    k_zero<<<(n + 1023) / 1024, 1024>>>(n);
    // launch 2: histogram + weight convert (independent, fused)
    k_histcvt<<<hb + 192, 256>>>(dst, e, hb, Wl1, Wr1, Wl2, Wr2);
    // launch 3: scan + fill
    k_scanfill<<<B, 512>>>(n, e);
    // launch 4 (ncu-captured): scatter + x-projection GEMM
    k_scatxproj<<<ntiles + SCAT_BLOCKS, 256, XP_SMEM>>>(
        x, b1, (uint32_t*)p_u, (uint32_t*)p_v, n, src, dst, e, ntiles);
    // launch 5: fused aggregation + relu
    k_aggrelu<<<(n + 7) / 8, 256>>>((const uint4*)p_u, (const uint2*)p_v,
                                    (uint2*)p_hh, n);
    // launch 6: layer-2 projections
    mma_zp<<<ntiles, 256, ZP_SMEM>>>(b2, (uint32_t*)p_z, (uint32_t*)p_pre, n);
    // launch 7: fused aggregation + log_softmax
    k_agg64out<<<(n + 7) / 8, 256>>>((const uint4*)p_z, (const uint4*)p_pre,
                                     (float4*)out, n);
}

// round 14
// speedup vs baseline: 2.5912x; 1.0550x over previous
#include <cuda_runtime.h>
#include <cuda_fp16.h>
#include <stdint.h>
#include <math.h>

#define NMAX 100000
#define EMAX 1600000
#define FULL 0xffffffffu

// ---------------- scratch (static device globals; no allocations) ----------
__device__ int      g_count[NMAX];
__device__ int      g_rowstart[NMAX + 1];
__device__ int      g_cursor[NMAX];
__device__ int      g_srcs[EMAX];
__device__ float    g_invdeg[NMAX];
__device__ int      g_bflag[64];
__device__ int      g_bincl[64];
__device__ uint4    g_u[NMAX * 16];    // x @ Wl1, fp16 (128 halves/row)
__device__ uint32_t g_v[NMAX * 64];    // x @ Wr1 + b1, fp16 (128 halves/row)
__device__ uint2    g_hh[NMAX * 32];   // hidden, fp16 (128 halves/row)
__device__ uint4    g_z[NMAX * 8];     // h @ Wl2, fp16 (64 halves/row)
__device__ uint32_t g_pre[NMAX * 32];  // h @ Wr2 + b2, fp16 (64 halves/row)
__device__ uint4    g_w1h[256 * 16];   // [Wl1|Wr1]^T fp16: [n=256][k=128]
__device__ uint4    g_w2h[128 * 16];   // [Wl2|Wr2]^T fp16: [n=128][k=128]

// ---------------- helpers ---------------------------------------------------
__device__ __forceinline__ uint32_t smem_u32(const void* p) {
    uint32_t a;
    asm("{ .reg .u64 t; cvta.to.shared.u64 t, %1; cvt.u32.u64 %0, t; }" : "=r"(a) : "l"(p));
    return a;
}
__device__ __forceinline__ unsigned int packh2(float a, float b) {
    __half2 h = __floats2half2_rn(a, b);
    return *(unsigned int*)&h;
}
__device__ __forceinline__ void acc8(float* a, uint4 w) {
    float2 f0 = __half22float2(*(__half2*)&w.x);
    float2 f1 = __half22float2(*(__half2*)&w.y);
    float2 f2 = __half22float2(*(__half2*)&w.z);
    float2 f3 = __half22float2(*(__half2*)&w.w);
    a[0] += f0.x; a[1] += f0.y; a[2] += f1.x; a[3] += f1.y;
    a[4] += f2.x; a[5] += f2.y; a[6] += f3.x; a[7] += f3.y;
}
__device__ __forceinline__ void accpair(float* a, uint4 w0, uint4 w1) {
    __half2 s0 = __hadd2(*(__half2*)&w0.x, *(__half2*)&w1.x);
    __half2 s1 = __hadd2(*(__half2*)&w0.y, *(__half2*)&w1.y);
    __half2 s2 = __hadd2(*(__half2*)&w0.z, *(__half2*)&w1.z);
    __half2 s3 = __hadd2(*(__half2*)&w0.w, *(__half2*)&w1.w);
    float2 f0 = __half22float2(s0);
    float2 f1 = __half22float2(s1);
    float2 f2 = __half22float2(s2);
    float2 f3 = __half22float2(s3);
    a[0] += f0.x; a[1] += f0.y; a[2] += f1.x; a[3] += f1.y;
    a[4] += f2.x; a[5] += f2.y; a[6] += f3.x; a[7] += f3.y;
}

#define LDSM4(r, addr)                                                                \
    asm volatile("ldmatrix.sync.aligned.m8n8.x4.shared.b16 {%0,%1,%2,%3}, [%4];"      \
        : "=r"((r)[0]), "=r"((r)[1]), "=r"((r)[2]), "=r"((r)[3]) : "r"(addr))

#define MMA16816(d, a, b0, b1)                                                        \
    asm volatile("mma.sync.aligned.m16n8k16.row.col.f32.f16.f16.f32 "                 \
        "{%0,%1,%2,%3}, {%4,%5,%6,%7}, {%8,%9}, {%0,%1,%2,%3};"                       \
        : "+f"((d)[0]), "+f"((d)[1]), "+f"((d)[2]), "+f"((d)[3])                      \
        : "r"((a)[0]), "r"((a)[1]), "r"((a)[2]), "r"((a)[3]), "r"(b0), "r"(b1))

// ---------------- CSR build -------------------------------------------------
__global__ void k_zero(int n) {
    int i = blockIdx.x * blockDim.x + threadIdx.x;
    if (i < n) g_count[i] = 0;
    if (i < 64) g_bflag[i] = 0;
}

// fused: histogram (int4-vectorized) + weight convert
__global__ void k_histcvt(const int4* __restrict__ dst4, int e4, int rem, int hb,
                          const int* __restrict__ dst,
                          const float* __restrict__ Wl1, const float* __restrict__ Wr1,
                          const float* __restrict__ Wl2, const float* __restrict__ Wr2)
{
    const int bid = blockIdx.x;
    if (bid < hb) {
        int i = bid * 256 + threadIdx.x;
        if (i < e4) {
            int4 d = __ldg(&dst4[i]);
            atomicAdd(&g_count[d.x], 1);
            atomicAdd(&g_count[d.y], 1);
            atomicAdd(&g_count[d.z], 1);
            atomicAdd(&g_count[d.w], 1);
        }
        if (i < rem) atomicAdd(&g_count[dst[e4 * 4 + i]], 1);
    } else {
        int i = (bid - hb) * 256 + threadIdx.x;
        __half* w1 = (__half*)g_w1h;
        __half* w2 = (__half*)g_w2h;
        if (i < 256 * 128) {
            int nn = i >> 7, k = i & 127;
            float v = (nn < 128) ? Wl1[k * 128 + nn] : Wr1[k * 128 + (nn - 128)];
            w1[i] = __float2half_rn(v);
        } else if (i < 256 * 128 + 128 * 128) {
            int j = i - 256 * 128;
            int nn = j >> 7, k = j & 127;
            float v = (nn < 64) ? Wl2[k * 64 + nn] : Wr2[k * 64 + (nn - 64)];
            w2[j] = __float2half_rn(v);
        }
    }
}

__global__ void k_scanfill(int n, int e) {
    const int tid = threadIdx.x;
    const int lane = tid & 31, wid = tid >> 5;
    const int b = blockIdx.x;
    const int gbase = b * 2048 + tid * 4;
    int c[4];
    int s = 0;
#pragma unroll
    for (int j = 0; j < 4; j++) {
        c[j] = (gbase + j < n) ? g_count[gbase + j] : 0;
        s += c[j];
    }
    int incl = s;
#pragma unroll
    for (int off = 1; off < 32; off <<= 1) {
        int t = __shfl_up_sync(FULL, incl, off);
        if (lane >= off) incl += t;
    }
    __shared__ int wsum[16];
    __shared__ int sprev;
    if (lane == 31) wsum[wid] = incl;
    __syncthreads();
    if (tid < 16) {
        int v = wsum[tid];
#pragma unroll
        for (int off = 1; off < 16; off <<= 1) {
            int t = __shfl_up_sync(0xffffu, v, off);
            if (tid >= off) v += t;
        }
        wsum[tid] = v;
    }
    __syncthreads();
    if (tid == 0) {
        int prev = 0;
        if (b > 0) {
            while (atomicAdd(&g_bflag[b - 1], 0) == 0) {}
            prev = atomicAdd(&g_bincl[b - 1], 0);
        }
        g_bincl[b] = prev + wsum[15];
        __threadfence();
        atomicExch(&g_bflag[b], 1);
        sprev = prev;
        if (b == 0) g_rowstart[n] = e;
    }
    __syncthreads();
    int base = sprev + (incl - s) + (wid ? wsum[wid - 1] : 0);
#pragma unroll
    for (int j = 0; j < 4; j++) {
        if (gbase + j < n) {
            g_rowstart[gbase + j] = base;
            g_cursor[gbase + j] = base;
            g_invdeg[gbase + j] = 1.0f / fmaxf((float)c[j], 1.0f);
            base += c[j];
        }
    }
}

// ---------------- fused: scatter + N-split mma.sync GEMM 1 ------------------
// blocks [0, 2*ntiles): GEMM for (tile t = bid>>1, half q = bid&1):
//   q=0: u = fp16(x@Wl1); q=1: v = fp16(x@Wr1 + b1).
// blocks [2*ntiles, +SCAT): CSR scatter.
// smem: A[128][136] (34816B) + Bhalf[128][136] (34816B) = 69632B -> 3 CTAs/SM.
#define SCAT_BLOCKS 1024
#define XP_SMEM (34816 + 34816)
__global__ __launch_bounds__(256, 3)
void k_scatxproj(const float* __restrict__ x, const float* __restrict__ bias,
                 uint32_t* __restrict__ u32, uint32_t* __restrict__ v32, int n,
                 const int* __restrict__ src, const int* __restrict__ dst,
                 int e, int ntiles)
{
    extern __shared__ char smem[];
    const int tid = threadIdx.x;

    if ((int)blockIdx.x >= 2 * ntiles) {
        const int sb = blockIdx.x - 2 * ntiles;
        for (int i = sb * 256 + tid; i < e; i += SCAT_BLOCKS * 256) {
            int pos = atomicAdd(&g_cursor[dst[i]], 1);
            g_srcs[pos] = src[i];
        }
        return;
    }

    const uint32_t sbA = smem_u32(smem);
    const uint32_t sbB = sbA + 34816;
    const int wid = tid >> 5, lane = tid & 31;
    const int t = blockIdx.x >> 1, q = blockIdx.x & 1;
    const int row0T = t * 128;

    // stage B half: rows [q*128, q*128+128) of [Wl1|Wr1]^T
    {
        const uint4* wt = (const uint4*)g_w1h;
        uint4* sB4 = (uint4*)(smem + 34816);
        for (int i = tid; i < 2048; i += 256) {
            int r = i >> 4, hc = i & 15;
            sB4[r * 17 + hc] = __ldg(&wt[(q * 128 + r) * 16 + hc]);
        }
    }
    // stage A: x tile fp32 -> fp16
    {
        uint4* sA4 = (uint4*)smem;
        const float4* x4 = (const float4*)x;
        for (int i = tid; i < 2048; i += 256) {
            int r = i >> 4, hc = i & 15;
            int gr = row0T + r;
            uint4 val = make_uint4(0, 0, 0, 0);
            if (gr < n) {
                float4 f0 = __ldg(&x4[gr * 32 + hc * 2]);
                float4 f1 = __ldg(&x4[gr * 32 + hc * 2 + 1]);
                val = make_uint4(packh2(f0.x, f0.y), packh2(f0.z, f0.w),
                                 packh2(f1.x, f1.y), packh2(f1.z, f1.w));
            }
            sA4[r * 17 + hc] = val;
        }
    }
    __syncthreads();

    const int wm = wid & 3, wn = wid >> 2;   // 4 m-slots x 2 n-slots (64 cols each)
    const int gid = lane >> 2, tig = lane & 3;

    float acc[2][8][4];
#pragma unroll
    for (int mt = 0; mt < 2; mt++)
#pragma unroll
        for (int nt = 0; nt < 8; nt++)
#pragma unroll
            for (int qq = 0; qq < 4; qq++) acc[mt][nt][qq] = 0.f;

    const uint32_t aRow = (uint32_t)(wm * 32 + (lane & 15));
    const uint32_t aColOff = 8u * (lane >> 4);
    const uint32_t bRow = (uint32_t)(wn * 64 + (lane & 7) + 8 * (lane >> 4));
    const uint32_t bColOff = 8u * ((lane >> 3) & 1);

#pragma unroll
    for (int k0 = 0; k0 < 8; k0++) {
        const uint32_t kk = (uint32_t)k0 * 16;
        uint32_t a[2][4];
#pragma unroll
        for (int mt = 0; mt < 2; mt++) {
            uint32_t addr = sbA + ((aRow + mt * 16) * 136 + kk + aColOff) * 2;
            LDSM4(a[mt], addr);
        }
#pragma unroll
        for (int np = 0; np < 4; np++) {
            uint32_t addr = sbB + ((bRow + np * 16) * 136 + kk + bColOff) * 2;
            uint32_t b[4];
            LDSM4(b, addr);
#pragma unroll
            for (int mt = 0; mt < 2; mt++) {
                MMA16816(acc[mt][np * 2],     a[mt], b[0], b[1]);
                MMA16816(acc[mt][np * 2 + 1], a[mt], b[2], b[3]);
            }
        }
    }

#pragma unroll
    for (int mt = 0; mt < 2; mt++) {
        int r0 = row0T + wm * 32 + mt * 16 + gid;
        int r1 = r0 + 8;
        const int cb = wn * 32;   // uint32 col base within 64-wide row
        if (q == 0) {
#pragma unroll
            for (int nt = 0; nt < 8; nt++) {
                if (r0 < n) u32[r0 * 64 + cb + nt * 4 + tig] = packh2(acc[mt][nt][0], acc[mt][nt][1]);
                if (r1 < n) u32[r1 * 64 + cb + nt * 4 + tig] = packh2(acc[mt][nt][2], acc[mt][nt][3]);
            }
        } else {
            const float2* b2 = (const float2*)bias;
#pragma unroll
            for (int nt = 0; nt < 8; nt++) {
                float2 bb = __ldg(&b2[cb + nt * 4 + tig]);
                if (r0 < n) v32[r0 * 64 + cb + nt * 4 + tig] =
                    packh2(acc[mt][nt][0] + bb.x, acc[mt][nt][1] + bb.y);
                if (r1 < n) v32[r1 * 64 + cb + nt * 4 + tig] =
                    packh2(acc[mt][nt][2] + bb.x, acc[mt][nt][3] + bb.y);
            }
        }
    }
}

// ---------------- mma.sync GEMM 2: [z | pre] = h @ [Wl2 | Wr2] --------------
#define ZP_SMEM (34816 + 34816)
__global__ __launch_bounds__(256, 3)
void mma_zp(const float* __restrict__ bias,
            uint32_t* __restrict__ z32, uint32_t* __restrict__ pre32, int n)
{
    extern __shared__ char smem[];
    const uint32_t sbA = smem_u32(smem);
    const uint32_t sbB = sbA + 34816;
    const int tid = threadIdx.x, wid = tid >> 5, lane = tid & 31;
    const int row0T = blockIdx.x * 128;

    {
        const uint4* wt = (const uint4*)g_w2h;
        uint4* sB4 = (uint4*)(smem + 34816);
        for (int i = tid; i < 2048; i += 256) {
            int r = i >> 4, hc = i & 15;
            sB4[r * 17 + hc] = __ldg(&wt[r * 16 + hc]);
        }
    }
    {
        uint4* sA4 = (uint4*)smem;
        const uint4* h16 = (const uint4*)g_hh;
        for (int i = tid; i < 2048; i += 256) {
            int r = i >> 4, hc = i & 15;
            int gr = row0T + r;
            uint4 val = make_uint4(0, 0, 0, 0);
            if (gr < n) val = __ldg(&h16[gr * 16 + hc]);
            sA4[r * 17 + hc] = val;
        }
    }
    __syncthreads();

    const int wm = wid & 3, gq = wid >> 2;
    const int gid = lane >> 2, tig = lane & 3;

    float acc[2][8][4];
#pragma unroll
    for (int mt = 0; mt < 2; mt++)
#pragma unroll
        for (int nt = 0; nt < 8; nt++)
#pragma unroll
            for (int qq = 0; qq < 4; qq++) acc[mt][nt][qq] = 0.f;

    const uint32_t aRow = (uint32_t)(wm * 32 + (lane & 15));
    const uint32_t aColOff = 8u * (lane >> 4);
    const uint32_t bRow = (uint32_t)(gq * 64 + (lane & 7) + 8 * (lane >> 4));
    const uint32_t bColOff = 8u * ((lane >> 3) & 1);

#pragma unroll
    for (int k0 = 0; k0 < 8; k0++) {
        const uint32_t kk = (uint32_t)k0 * 16;
        uint32_t a[2][4];
#pragma unroll
        for (int mt = 0; mt < 2; mt++) {
            uint32_t addr = sbA + ((aRow + mt * 16) * 136 + kk + aColOff) * 2;
            LDSM4(a[mt], addr);
        }
#pragma unroll
        for (int np = 0; np < 4; np++) {
            uint32_t addr = sbB + ((bRow + np * 16) * 136 + kk + bColOff) * 2;
            uint32_t b[4];
            LDSM4(b, addr);
#pragma unroll
            for (int mt = 0; mt < 2; mt++) {
                MMA16816(acc[mt][np * 2],     a[mt], b[0], b[1]);
                MMA16816(acc[mt][np * 2 + 1], a[mt], b[2], b[3]);
            }
        }
    }

#pragma unroll
    for (int mt = 0; mt < 2; mt++) {
        int r0 = row0T + wm * 32 + mt * 16 + gid;
        int r1 = r0 + 8;
        if (gq == 0) {
#pragma unroll
            for (int nt = 0; nt < 8; nt++) {
                if (r0 < n) z32[r0 * 32 + nt * 4 + tig] = packh2(acc[mt][nt][0], acc[mt][nt][1]);
                if (r1 < n) z32[r1 * 32 + nt * 4 + tig] = packh2(acc[mt][nt][2], acc[mt][nt][3]);
            }
        } else {
            const float2* b2 = (const float2*)bias;
#pragma unroll
            for (int nt = 0; nt < 8; nt++) {
                float2 bb = __ldg(&b2[nt * 4 + tig]);
                if (r0 < n) pre32[r0 * 32 + nt * 4 + tig] =
                    packh2(acc[mt][nt][0] + bb.x, acc[mt][nt][1] + bb.y);
                if (r1 < n) pre32[r1 * 32 + nt * 4 + tig] =
                    packh2(acc[mt][nt][2] + bb.x, acc[mt][nt][3] + bb.y);
            }
        }
    }
}

// ---------------- fused: h = fp16(relu(mean_agg(u_fp16) + v_fp16)) ----------
__global__ void k_aggrelu(const uint4* __restrict__ u, const uint2* __restrict__ v,
                          uint2* __restrict__ hh, int n)
{
    int node = blockIdx.x * (blockDim.x >> 5) + (threadIdx.x >> 5);
    if (node >= n) return;
    const int lane = threadIdx.x & 31;
    const int pair = lane >> 4, c = lane & 15;
    const int beg = g_rowstart[node];
    const int cnt = g_rowstart[node + 1] - beg;

    float a0[8] = {0,0,0,0,0,0,0,0};

    for (int base = 0; base < cnt; base += 32) {
        const int m = min(32, cnt - base);
        int idx = (lane < m) ? __ldg(&g_srcs[beg + base + lane]) : 0;
        int j = 0;
        for (; j + 3 < m; j += 4) {
            int s0 = __shfl_sync(FULL, idx, j + pair);
            int s1 = __shfl_sync(FULL, idx, j + 2 + pair);
            uint4 w0 = __ldg(&u[s0 * 16 + c]);
            uint4 w1 = __ldg(&u[s1 * 16 + c]);
            accpair(a0, w0, w1);
        }
        for (; j < m; j += 2) {
            int s0 = __shfl_sync(FULL, idx, (j + pair) & 31);
            if (j + pair < m) {
                uint4 w0 = __ldg(&u[s0 * 16 + c]);
                acc8(a0, w0);
            }
        }
    }
#pragma unroll
    for (int i = 0; i < 8; i++)
        a0[i] += __shfl_xor_sync(FULL, a0[i], 16);

    const float inv = g_invdeg[node];
    uint2 vv = __ldg(&v[node * 32 + c * 2 + pair]);
    float2 v0 = __half22float2(*(__half2*)&vv.x);
    float2 v1 = __half22float2(*(__half2*)&vv.y);
    const int k0 = pair * 4;
    float r0 = fmaxf(a0[k0 + 0] * inv + v0.x, 0.f);
    float r1 = fmaxf(a0[k0 + 1] * inv + v0.y, 0.f);
    float r2 = fmaxf(a0[k0 + 2] * inv + v1.x, 0.f);
    float r3 = fmaxf(a0[k0 + 3] * inv + v1.y, 0.f);
    hh[node * 32 + c * 2 + pair] = make_uint2(packh2(r0, r1), packh2(r2, r3));
}

// ---------------- fused: out = log_softmax(mean_agg(z_fp16) + pre_fp16) -----
__global__ void k_agg64out(const uint4* __restrict__ z, const uint4* __restrict__ pre,
                           float4* __restrict__ out, int n)
{
    int node = blockIdx.x * (blockDim.x >> 5) + (threadIdx.x >> 5);
    if (node >= n) return;
    const int lane = threadIdx.x & 31;
    const int quad = lane >> 3, c = lane & 7;
    const int beg = g_rowstart[node];
    const int cnt = g_rowstart[node + 1] - beg;

    float a0[8] = {0,0,0,0,0,0,0,0};

    for (int base = 0; base < cnt; base += 32) {
        const int m = min(32, cnt - base);
        int idx = (lane < m) ? __ldg(&g_srcs[beg + base + lane]) : 0;
        int j = 0;
        for (; j + 7 < m; j += 8) {
            int s0 = __shfl_sync(FULL, idx, j + quad);
            int s1 = __shfl_sync(FULL, idx, j + 4 + quad);
            uint4 w0 = __ldg(&z[s0 * 8 + c]);
            uint4 w1 = __ldg(&z[s1 * 8 + c]);
            accpair(a0, w0, w1);
        }
        for (; j < m; j += 4) {
            int s0 = __shfl_sync(FULL, idx, (j + quad) & 31);
            if (j + quad < m) {
                uint4 w0 = __ldg(&z[s0 * 8 + c]);
                acc8(a0, w0);
            }
        }
    }
#pragma unroll
    for (int i = 0; i < 8; i++) {
        a0[i] += __shfl_xor_sync(FULL, a0[i], 8);
        a0[i] += __shfl_xor_sync(FULL, a0[i], 16);
    }
    const float inv = g_invdeg[node];
    uint4 pp = __ldg(&pre[node * 8 + c]);
    float2 p0 = __half22float2(*(__half2*)&pp.x);
    float2 p1 = __half22float2(*(__half2*)&pp.y);
    float2 p2 = __half22float2(*(__half2*)&pp.z);
    float2 p3 = __half22float2(*(__half2*)&pp.w);
    float vv[8];
    vv[0] = a0[0] * inv + p0.x; vv[1] = a0[1] * inv + p0.y;
    vv[2] = a0[2] * inv + p1.x; vv[3] = a0[3] * inv + p1.y;
    vv[4] = a0[4] * inv + p2.x; vv[5] = a0[5] * inv + p2.y;
    vv[6] = a0[6] * inv + p3.x; vv[7] = a0[7] * inv + p3.y;

    float m8 = vv[0];
#pragma unroll
    for (int i = 1; i < 8; i++) m8 = fmaxf(m8, vv[i]);
#pragma unroll
    for (int off = 4; off > 0; off >>= 1) m8 = fmaxf(m8, __shfl_xor_sync(FULL, m8, off));
    float s = 0.f;
#pragma unroll
    for (int i = 0; i < 8; i++) s += expf(vv[i] - m8);
#pragma unroll
    for (int off = 4; off > 0; off >>= 1) s += __shfl_xor_sync(FULL, s, off);
    float lse = m8 + logf(s);

    if (quad < 2) {
        const int k0 = quad * 4;
        out[node * 16 + c * 2 + quad] =
            make_float4(vv[k0 + 0] - lse, vv[k0 + 1] - lse,
                        vv[k0 + 2] - lse, vv[k0 + 3] - lse);
    }
}

// ---------------- launch -----------------------------------------------------
extern "C" void kernel_launch(void* const* d_in, const int* in_sizes, int n_in,
                              void* d_out, int out_size)
{
    const float* x   = (const float*)d_in[0];
    const int*   ei  = (const int*)d_in[1];
    const float* Wl1 = (const float*)d_in[2];
    const float* Wr1 = (const float*)d_in[3];
    const float* b1  = (const float*)d_in[4];
    const float* Wl2 = (const float*)d_in[5];
    const float* Wr2 = (const float*)d_in[6];
    const float* b2  = (const float*)d_in[7];
    float* out = (float*)d_out;

    const int n = in_sizes[0] / 128;
    const int e = in_sizes[1] / 2;
    const int* src = ei;
    const int* dst = ei + e;
    const int ntiles = (n + 127) / 128;

    static bool attr_done = false;
    if (!attr_done) {
        cudaFuncSetAttribute(k_scatxproj, cudaFuncAttributeMaxDynamicSharedMemorySize, XP_SMEM);
        cudaFuncSetAttribute(mma_zp,      cudaFuncAttributeMaxDynamicSharedMemorySize, ZP_SMEM);
        attr_done = true;
    }

    void *p_u = nullptr, *p_v = nullptr, *p_hh = nullptr, *p_z = nullptr, *p_pre = nullptr;
    cudaGetSymbolAddress(&p_u, g_u);
    cudaGetSymbolAddress(&p_v, g_v);
    cudaGetSymbolAddress(&p_hh, g_hh);
    cudaGetSymbolAddress(&p_z, g_z);
    cudaGetSymbolAddress(&p_pre, g_pre);

    const int B = (n + 2047) / 2048;
    const int e4 = e / 4;
    const int rem = e - e4 * 4;
    const int hb = (e4 + 255) / 256;

    // launch 1: zero counts + flags
    k_zero<<<(n + 1023) / 1024, 1024>>>(n);
    // launch 2: histogram (int4) + weight convert (independent, fused)
    k_histcvt<<<hb + 192, 256>>>((const int4*)dst, e4, rem, hb, dst,
                                 Wl1, Wr1, Wl2, Wr2);
    // launch 3: scan + fill
    k_scanfill<<<B, 512>>>(n, e);
    // launch 4 (ncu-captured): scatter + N-split x-projection GEMM
    k_scatxproj<<<2 * ntiles + SCAT_BLOCKS, 256, XP_SMEM>>>(
        x, b1, (uint32_t*)p_u, (uint32_t*)p_v, n, src, dst, e, ntiles);
    // launch 5: fused aggregation + relu
    k_aggrelu<<<(n + 7) / 8, 256>>>((const uint4*)p_u, (const uint2*)p_v,
                                    (uint2*)p_hh, n);
    // launch 6: layer-2 projections
    mma_zp<<<ntiles, 256, ZP_SMEM>>>(b2, (uint32_t*)p_z, (uint32_t*)p_pre, n);
    // launch 7: fused aggregation + log_softmax
    k_agg64out<<<(n + 7) / 8, 256>>>((const uint4*)p_z, (const uint4*)p_pre,
                                     (float4*)out, n);
}

// round 15
// speedup vs baseline: 2.6962x; 1.0405x over previous
#include <cuda_runtime.h>
#include <cuda_fp16.h>
#include <stdint.h>
#include <math.h>

#define NMAX 100000
#define EMAX 1600000
#define FULL 0xffffffffu

// ---------------- scratch (static device globals; no allocations) ----------
__device__ int      g_count[NMAX];
__device__ int      g_rowstart[NMAX + 1];
__device__ int      g_cursor[NMAX];
__device__ int      g_srcs[EMAX];
__device__ float    g_invdeg[NMAX];
__device__ int      g_bflag[64];
__device__ int      g_bincl[64];
__device__ uint4    g_u[NMAX * 16];    // x @ Wl1, fp16 (128 halves/row)
__device__ uint32_t g_v[NMAX * 64];    // x @ Wr1 + b1, fp16 (128 halves/row)
__device__ uint2    g_hh[NMAX * 32];   // hidden, fp16 (128 halves/row)
__device__ uint4    g_z[NMAX * 8];     // h @ Wl2, fp16 (64 halves/row)
__device__ uint32_t g_pre[NMAX * 32];  // h @ Wr2 + b2, fp16 (64 halves/row)
__device__ uint4    g_w1h[256 * 16];   // [Wl1|Wr1]^T fp16: [n=256][k=128]
__device__ uint4    g_w2h[128 * 16];   // [Wl2|Wr2]^T fp16: [n=128][k=128]

// ---------------- helpers ---------------------------------------------------
__device__ __forceinline__ uint32_t smem_u32(const void* p) {
    uint32_t a;
    asm("{ .reg .u64 t; cvta.to.shared.u64 t, %1; cvt.u32.u64 %0, t; }" : "=r"(a) : "l"(p));
    return a;
}
__device__ __forceinline__ unsigned int packh2(float a, float b) {
    __half2 h = __floats2half2_rn(a, b);
    return *(unsigned int*)&h;
}
__device__ __forceinline__ void acc8(float* a, uint4 w) {
    float2 f0 = __half22float2(*(__half2*)&w.x);
    float2 f1 = __half22float2(*(__half2*)&w.y);
    float2 f2 = __half22float2(*(__half2*)&w.z);
    float2 f3 = __half22float2(*(__half2*)&w.w);
    a[0] += f0.x; a[1] += f0.y; a[2] += f1.x; a[3] += f1.y;
    a[4] += f2.x; a[5] += f2.y; a[6] += f3.x; a[7] += f3.y;
}
__device__ __forceinline__ void accpair(float* a, uint4 w0, uint4 w1) {
    __half2 s0 = __hadd2(*(__half2*)&w0.x, *(__half2*)&w1.x);
    __half2 s1 = __hadd2(*(__half2*)&w0.y, *(__half2*)&w1.y);
    __half2 s2 = __hadd2(*(__half2*)&w0.z, *(__half2*)&w1.z);
    __half2 s3 = __hadd2(*(__half2*)&w0.w, *(__half2*)&w1.w);
    float2 f0 = __half22float2(s0);
    float2 f1 = __half22float2(s1);
    float2 f2 = __half22float2(s2);
    float2 f3 = __half22float2(s3);
    a[0] += f0.x; a[1] += f0.y; a[2] += f1.x; a[3] += f1.y;
    a[4] += f2.x; a[5] += f2.y; a[6] += f3.x; a[7] += f3.y;
}

#define LDSM4(r, addr)                                                                \
    asm volatile("ldmatrix.sync.aligned.m8n8.x4.shared.b16 {%0,%1,%2,%3}, [%4];"      \
        : "=r"((r)[0]), "=r"((r)[1]), "=r"((r)[2]), "=r"((r)[3]) : "r"(addr))

#define MMA16816(d, a, b0, b1)                                                        \
    asm volatile("mma.sync.aligned.m16n8k16.row.col.f32.f16.f16.f32 "                 \
        "{%0,%1,%2,%3}, {%4,%5,%6,%7}, {%8,%9}, {%0,%1,%2,%3};"                       \
        : "+f"((d)[0]), "+f"((d)[1]), "+f"((d)[2]), "+f"((d)[3])                      \
        : "r"((a)[0]), "r"((a)[1]), "r"((a)[2]), "r"((a)[3]), "r"(b0), "r"(b1))

// ---------------- CSR build -------------------------------------------------
__global__ void k_zero(int n) {
    int i = blockIdx.x * blockDim.x + threadIdx.x;
    if (i < n) g_count[i] = 0;
    if (i < 64) g_bflag[i] = 0;
}

// fused: histogram (int4-vectorized) + weight convert
__global__ void k_histcvt(const int4* __restrict__ dst4, int e4, int rem, int hb,
                          const int* __restrict__ dst,
                          const float* __restrict__ Wl1, const float* __restrict__ Wr1,
                          const float* __restrict__ Wl2, const float* __restrict__ Wr2)
{
    const int bid = blockIdx.x;
    if (bid < hb) {
        int i = bid * 256 + threadIdx.x;
        if (i < e4) {
            int4 d = __ldg(&dst4[i]);
            atomicAdd(&g_count[d.x], 1);
            atomicAdd(&g_count[d.y], 1);
            atomicAdd(&g_count[d.z], 1);
            atomicAdd(&g_count[d.w], 1);
        }
        if (i < rem) atomicAdd(&g_count[dst[e4 * 4 + i]], 1);
    } else {
        int i = (bid - hb) * 256 + threadIdx.x;
        __half* w1 = (__half*)g_w1h;
        __half* w2 = (__half*)g_w2h;
        if (i < 256 * 128) {
            int nn = i >> 7, k = i & 127;
            float v = (nn < 128) ? Wl1[k * 128 + nn] : Wr1[k * 128 + (nn - 128)];
            w1[i] = __float2half_rn(v);
        } else if (i < 256 * 128 + 128 * 128) {
            int j = i - 256 * 128;
            int nn = j >> 7, k = j & 127;
            float v = (nn < 64) ? Wl2[k * 64 + nn] : Wr2[k * 64 + (nn - 64)];
            w2[j] = __float2half_rn(v);
        }
    }
}

__global__ void k_scanfill(int n, int e) {
    const int tid = threadIdx.x;
    const int lane = tid & 31, wid = tid >> 5;
    const int b = blockIdx.x;
    const int gbase = b * 2048 + tid * 4;
    int c[4];
    int s = 0;
#pragma unroll
    for (int j = 0; j < 4; j++) {
        c[j] = (gbase + j < n) ? g_count[gbase + j] : 0;
        s += c[j];
    }
    int incl = s;
#pragma unroll
    for (int off = 1; off < 32; off <<= 1) {
        int t = __shfl_up_sync(FULL, incl, off);
        if (lane >= off) incl += t;
    }
    __shared__ int wsum[16];
    __shared__ int sprev;
    if (lane == 31) wsum[wid] = incl;
    __syncthreads();
    if (tid < 16) {
        int v = wsum[tid];
#pragma unroll
        for (int off = 1; off < 16; off <<= 1) {
            int t = __shfl_up_sync(0xffffu, v, off);
            if (tid >= off) v += t;
        }
        wsum[tid] = v;
    }
    __syncthreads();
    if (tid == 0) {
        int prev = 0;
        if (b > 0) {
            while (atomicAdd(&g_bflag[b - 1], 0) == 0) {}
            prev = atomicAdd(&g_bincl[b - 1], 0);
        }
        g_bincl[b] = prev + wsum[15];
        __threadfence();
        atomicExch(&g_bflag[b], 1);
        sprev = prev;
        if (b == 0) g_rowstart[n] = e;
    }
    __syncthreads();
    int base = sprev + (incl - s) + (wid ? wsum[wid - 1] : 0);
#pragma unroll
    for (int j = 0; j < 4; j++) {
        if (gbase + j < n) {
            g_rowstart[gbase + j] = base;
            g_cursor[gbase + j] = base;
            g_invdeg[gbase + j] = 1.0f / fmaxf((float)c[j], 1.0f);
            base += c[j];
        }
    }
}

// ---------------- fused: scatter + mma.sync GEMM 1 (A staged once) ----------
// blocks [0, ntiles): GEMM tile; A staged once, two B-half passes (q=0 -> u,
// q=1 -> v+bias). blocks [ntiles, +SCAT): CSR scatter.
// smem: A[128][136] (34816B) + Bhalf[128][136] (34816B) = 69632B -> 3 CTAs/SM.
#define SCAT_BLOCKS 1024
#define XP_SMEM (34816 + 34816)
__global__ __launch_bounds__(256, 3)
void k_scatxproj(const float* __restrict__ x, const float* __restrict__ bias,
                 uint32_t* __restrict__ u32, uint32_t* __restrict__ v32, int n,
                 const int* __restrict__ src, const int* __restrict__ dst,
                 int e, int ntiles)
{
    extern __shared__ char smem[];
    const int tid = threadIdx.x;

    if ((int)blockIdx.x >= ntiles) {
        const int sb = blockIdx.x - ntiles;
        for (int i = sb * 256 + tid; i < e; i += SCAT_BLOCKS * 256) {
            int pos = atomicAdd(&g_cursor[dst[i]], 1);
            g_srcs[pos] = src[i];
        }
        return;
    }

    const uint32_t sbA = smem_u32(smem);
    const uint32_t sbB = sbA + 34816;
    const int wid = tid >> 5, lane = tid & 31;
    const int row0T = blockIdx.x * 128;

    // stage A once: x tile fp32 -> fp16
    {
        uint4* sA4 = (uint4*)smem;
        const float4* x4 = (const float4*)x;
        for (int i = tid; i < 2048; i += 256) {
            int r = i >> 4, hc = i & 15;
            int gr = row0T + r;
            uint4 val = make_uint4(0, 0, 0, 0);
            if (gr < n) {
                float4 f0 = __ldg(&x4[gr * 32 + hc * 2]);
                float4 f1 = __ldg(&x4[gr * 32 + hc * 2 + 1]);
                val = make_uint4(packh2(f0.x, f0.y), packh2(f0.z, f0.w),
                                 packh2(f1.x, f1.y), packh2(f1.z, f1.w));
            }
            sA4[r * 17 + hc] = val;
        }
    }

    const int wm = wid & 3, wn = wid >> 2;   // 4 m-slots x 2 n-slots (64 cols)
    const int gid = lane >> 2, tig = lane & 3;
    const uint32_t aRow = (uint32_t)(wm * 32 + (lane & 15));
    const uint32_t aColOff = 8u * (lane >> 4);
    const uint32_t bRow = (uint32_t)(wn * 64 + (lane & 7) + 8 * (lane >> 4));
    const uint32_t bColOff = 8u * ((lane >> 3) & 1);
    const uint4* wt = (const uint4*)g_w1h;
    uint4* sB4 = (uint4*)(smem + 34816);

#pragma unroll 1
    for (int q = 0; q < 2; q++) {
        // stage B half q: rows [q*128, q*128+128) of [Wl1|Wr1]^T
        for (int i = tid; i < 2048; i += 256) {
            int r = i >> 4, hc = i & 15;
            sB4[r * 17 + hc] = __ldg(&wt[(q * 128 + r) * 16 + hc]);
        }
        __syncthreads();

        float acc[2][8][4];
#pragma unroll
        for (int mt = 0; mt < 2; mt++)
#pragma unroll
            for (int nt = 0; nt < 8; nt++)
#pragma unroll
                for (int qq = 0; qq < 4; qq++) acc[mt][nt][qq] = 0.f;

#pragma unroll
        for (int k0 = 0; k0 < 8; k0++) {
            const uint32_t kk = (uint32_t)k0 * 16;
            uint32_t a[2][4];
#pragma unroll
            for (int mt = 0; mt < 2; mt++) {
                uint32_t addr = sbA + ((aRow + mt * 16) * 136 + kk + aColOff) * 2;
                LDSM4(a[mt], addr);
            }
#pragma unroll
            for (int np = 0; np < 4; np++) {
                uint32_t addr = sbB + ((bRow + np * 16) * 136 + kk + bColOff) * 2;
                uint32_t b[4];
                LDSM4(b, addr);
#pragma unroll
                for (int mt = 0; mt < 2; mt++) {
                    MMA16816(acc[mt][np * 2],     a[mt], b[0], b[1]);
                    MMA16816(acc[mt][np * 2 + 1], a[mt], b[2], b[3]);
                }
            }
        }
        __syncthreads();   // all warps done reading B before next restage

#pragma unroll
        for (int mt = 0; mt < 2; mt++) {
            int r0 = row0T + wm * 32 + mt * 16 + gid;
            int r1 = r0 + 8;
            const int cb = wn * 32;
            if (q == 0) {
#pragma unroll
                for (int nt = 0; nt < 8; nt++) {
                    if (r0 < n) u32[r0 * 64 + cb + nt * 4 + tig] = packh2(acc[mt][nt][0], acc[mt][nt][1]);
                    if (r1 < n) u32[r1 * 64 + cb + nt * 4 + tig] = packh2(acc[mt][nt][2], acc[mt][nt][3]);
                }
            } else {
                const float2* b2 = (const float2*)bias;
#pragma unroll
                for (int nt = 0; nt < 8; nt++) {
                    float2 bb = __ldg(&b2[cb + nt * 4 + tig]);
                    if (r0 < n) v32[r0 * 64 + cb + nt * 4 + tig] =
                        packh2(acc[mt][nt][0] + bb.x, acc[mt][nt][1] + bb.y);
                    if (r1 < n) v32[r1 * 64 + cb + nt * 4 + tig] =
                        packh2(acc[mt][nt][2] + bb.x, acc[mt][nt][3] + bb.y);
                }
            }
        }
    }
}

// ---------------- mma.sync GEMM 2: [z | pre] = h @ [Wl2 | Wr2] --------------
#define ZP_SMEM (34816 + 34816)
__global__ __launch_bounds__(256, 3)
void mma_zp(const float* __restrict__ bias,
            uint32_t* __restrict__ z32, uint32_t* __restrict__ pre32, int n)
{
    extern __shared__ char smem[];
    const uint32_t sbA = smem_u32(smem);
    const uint32_t sbB = sbA + 34816;
    const int tid = threadIdx.x, wid = tid >> 5, lane = tid & 31;
    const int row0T = blockIdx.x * 128;

    {
        const uint4* wt = (const uint4*)g_w2h;
        uint4* sB4 = (uint4*)(smem + 34816);
        for (int i = tid; i < 2048; i += 256) {
            int r = i >> 4, hc = i & 15;
            sB4[r * 17 + hc] = __ldg(&wt[r * 16 + hc]);
        }
    }
    {
        uint4* sA4 = (uint4*)smem;
        const uint4* h16 = (const uint4*)g_hh;
        for (int i = tid; i < 2048; i += 256) {
            int r = i >> 4, hc = i & 15;
            int gr = row0T + r;
            uint4 val = make_uint4(0, 0, 0, 0);
            if (gr < n) val = __ldg(&h16[gr * 16 + hc]);
            sA4[r * 17 + hc] = val;
        }
    }
    __syncthreads();

    const int wm = wid & 3, gq = wid >> 2;
    const int gid = lane >> 2, tig = lane & 3;

    float acc[2][8][4];
#pragma unroll
    for (int mt = 0; mt < 2; mt++)
#pragma unroll
        for (int nt = 0; nt < 8; nt++)
#pragma unroll
            for (int qq = 0; qq < 4; qq++) acc[mt][nt][qq] = 0.f;

    const uint32_t aRow = (uint32_t)(wm * 32 + (lane & 15));
    const uint32_t aColOff = 8u * (lane >> 4);
    const uint32_t bRow = (uint32_t)(gq * 64 + (lane & 7) + 8 * (lane >> 4));
    const uint32_t bColOff = 8u * ((lane >> 3) & 1);

#pragma unroll
    for (int k0 = 0; k0 < 8; k0++) {
        const uint32_t kk = (uint32_t)k0 * 16;
        uint32_t a[2][4];
#pragma unroll
        for (int mt = 0; mt < 2; mt++) {
            uint32_t addr = sbA + ((aRow + mt * 16) * 136 + kk + aColOff) * 2;
            LDSM4(a[mt], addr);
        }
#pragma unroll
        for (int np = 0; np < 4; np++) {
            uint32_t addr = sbB + ((bRow + np * 16) * 136 + kk + bColOff) * 2;
            uint32_t b[4];
            LDSM4(b, addr);
#pragma unroll
            for (int mt = 0; mt < 2; mt++) {
                MMA16816(acc[mt][np * 2],     a[mt], b[0], b[1]);
                MMA16816(acc[mt][np * 2 + 1], a[mt], b[2], b[3]);
            }
        }
    }

#pragma unroll
    for (int mt = 0; mt < 2; mt++) {
        int r0 = row0T + wm * 32 + mt * 16 + gid;
        int r1 = r0 + 8;
        if (gq == 0) {
#pragma unroll
            for (int nt = 0; nt < 8; nt++) {
                if (r0 < n) z32[r0 * 32 + nt * 4 + tig] = packh2(acc[mt][nt][0], acc[mt][nt][1]);
                if (r1 < n) z32[r1 * 32 + nt * 4 + tig] = packh2(acc[mt][nt][2], acc[mt][nt][3]);
            }
        } else {
            const float2* b2 = (const float2*)bias;
#pragma unroll
            for (int nt = 0; nt < 8; nt++) {
                float2 bb = __ldg(&b2[nt * 4 + tig]);
                if (r0 < n) pre32[r0 * 32 + nt * 4 + tig] =
                    packh2(acc[mt][nt][0] + bb.x, acc[mt][nt][1] + bb.y);
                if (r1 < n) pre32[r1 * 32 + nt * 4 + tig] =
                    packh2(acc[mt][nt][2] + bb.x, acc[mt][nt][3] + bb.y);
            }
        }
    }
}

// ---------------- fused: h = fp16(relu(mean_agg(u_fp16) + v_fp16)) ----------
__global__ void k_aggrelu(const uint4* __restrict__ u, const uint2* __restrict__ v,
                          uint2* __restrict__ hh, int n)
{
    int node = blockIdx.x * (blockDim.x >> 5) + (threadIdx.x >> 5);
    if (node >= n) return;
    const int lane = threadIdx.x & 31;
    const int pair = lane >> 4, c = lane & 15;
    const int beg = g_rowstart[node];
    const int cnt = g_rowstart[node + 1] - beg;

    float a0[8] = {0,0,0,0,0,0,0,0};

    for (int base = 0; base < cnt; base += 32) {
        const int m = min(32, cnt - base);
        int idx = (lane < m) ? __ldg(&g_srcs[beg + base + lane]) : 0;
        int j = 0;
        for (; j + 3 < m; j += 4) {
            int s0 = __shfl_sync(FULL, idx, j + pair);
            int s1 = __shfl_sync(FULL, idx, j + 2 + pair);
            uint4 w0 = __ldg(&u[s0 * 16 + c]);
            uint4 w1 = __ldg(&u[s1 * 16 + c]);
            accpair(a0, w0, w1);
        }
        for (; j < m; j += 2) {
            int s0 = __shfl_sync(FULL, idx, (j + pair) & 31);
            if (j + pair < m) {
                uint4 w0 = __ldg(&u[s0 * 16 + c]);
                acc8(a0, w0);
            }
        }
    }
#pragma unroll
    for (int i = 0; i < 8; i++)
        a0[i] += __shfl_xor_sync(FULL, a0[i], 16);

    const float inv = g_invdeg[node];
    uint2 vv = __ldg(&v[node * 32 + c * 2 + pair]);
    float2 v0 = __half22float2(*(__half2*)&vv.x);
    float2 v1 = __half22float2(*(__half2*)&vv.y);
    const int k0 = pair * 4;
    float r0 = fmaxf(a0[k0 + 0] * inv + v0.x, 0.f);
    float r1 = fmaxf(a0[k0 + 1] * inv + v0.y, 0.f);
    float r2 = fmaxf(a0[k0 + 2] * inv + v1.x, 0.f);
    float r3 = fmaxf(a0[k0 + 3] * inv + v1.y, 0.f);
    hh[node * 32 + c * 2 + pair] = make_uint2(packh2(r0, r1), packh2(r2, r3));
}

// ---------------- fused: out = log_softmax(mean_agg(z_fp16) + pre_fp16) -----
__global__ void k_agg64out(const uint4* __restrict__ z, const uint4* __restrict__ pre,
                           float4* __restrict__ out, int n)
{
    int node = blockIdx.x * (blockDim.x >> 5) + (threadIdx.x >> 5);
    if (node >= n) return;
    const int lane = threadIdx.x & 31;
    const int quad = lane >> 3, c = lane & 7;
    const int beg = g_rowstart[node];
    const int cnt = g_rowstart[node + 1] - beg;

    float a0[8] = {0,0,0,0,0,0,0,0};

    for (int base = 0; base < cnt; base += 32) {
        const int m = min(32, cnt - base);
        int idx = (lane < m) ? __ldg(&g_srcs[beg + base + lane]) : 0;
        int j = 0;
        for (; j + 7 < m; j += 8) {
            int s0 = __shfl_sync(FULL, idx, j + quad);
            int s1 = __shfl_sync(FULL, idx, j + 4 + quad);
            uint4 w0 = __ldg(&z[s0 * 8 + c]);
            uint4 w1 = __ldg(&z[s1 * 8 + c]);
            accpair(a0, w0, w1);
        }
        for (; j < m; j += 4) {
            int s0 = __shfl_sync(FULL, idx, (j + quad) & 31);
            if (j + quad < m) {
                uint4 w0 = __ldg(&z[s0 * 8 + c]);
                acc8(a0, w0);
            }
        }
    }
#pragma unroll
    for (int i = 0; i < 8; i++) {
        a0[i] += __shfl_xor_sync(FULL, a0[i], 8);
        a0[i] += __shfl_xor_sync(FULL, a0[i], 16);
    }
    const float inv = g_invdeg[node];
    uint4 pp = __ldg(&pre[node * 8 + c]);
    float2 p0 = __half22float2(*(__half2*)&pp.x);
    float2 p1 = __half22float2(*(__half2*)&pp.y);
    float2 p2 = __half22float2(*(__half2*)&pp.z);
    float2 p3 = __half22float2(*(__half2*)&pp.w);
    float vv[8];
    vv[0] = a0[0] * inv + p0.x; vv[1] = a0[1] * inv + p0.y;
    vv[2] = a0[2] * inv + p1.x; vv[3] = a0[3] * inv + p1.y;
    vv[4] = a0[4] * inv + p2.x; vv[5] = a0[5] * inv + p2.y;
    vv[6] = a0[6] * inv + p3.x; vv[7] = a0[7] * inv + p3.y;

    float m8 = vv[0];
#pragma unroll
    for (int i = 1; i < 8; i++) m8 = fmaxf(m8, vv[i]);
#pragma unroll
    for (int off = 4; off > 0; off >>= 1) m8 = fmaxf(m8, __shfl_xor_sync(FULL, m8, off));
    float s = 0.f;
#pragma unroll
    for (int i = 0; i < 8; i++) s += expf(vv[i] - m8);
#pragma unroll
    for (int off = 4; off > 0; off >>= 1) s += __shfl_xor_sync(FULL, s, off);
    float lse = m8 + logf(s);

    if (quad < 2) {
        const int k0 = quad * 4;
        out[node * 16 + c * 2 + quad] =
            make_float4(vv[k0 + 0] - lse, vv[k0 + 1] - lse,
                        vv[k0 + 2] - lse, vv[k0 + 3] - lse);
    }
}

// ---------------- launch -----------------------------------------------------
extern "C" void kernel_launch(void* const* d_in, const int* in_sizes, int n_in,
                              void* d_out, int out_size)
{
    const float* x   = (const float*)d_in[0];
    const int*   ei  = (const int*)d_in[1];
    const float* Wl1 = (const float*)d_in[2];
    const float* Wr1 = (const float*)d_in[3];
    const float* b1  = (const float*)d_in[4];
    const float* Wl2 = (const float*)d_in[5];
    const float* Wr2 = (const float*)d_in[6];
    const float* b2  = (const float*)d_in[7];
    float* out = (float*)d_out;

    const int n = in_sizes[0] / 128;
    const int e = in_sizes[1] / 2;
    const int* src = ei;
    const int* dst = ei + e;
    const int ntiles = (n + 127) / 128;

    static bool attr_done = false;
    if (!attr_done) {
        cudaFuncSetAttribute(k_scatxproj, cudaFuncAttributeMaxDynamicSharedMemorySize, XP_SMEM);
        cudaFuncSetAttribute(mma_zp,      cudaFuncAttributeMaxDynamicSharedMemorySize, ZP_SMEM);
        attr_done = true;
    }

    void *p_u = nullptr, *p_v = nullptr, *p_hh = nullptr, *p_z = nullptr, *p_pre = nullptr;
    cudaGetSymbolAddress(&p_u, g_u);
    cudaGetSymbolAddress(&p_v, g_v);
    cudaGetSymbolAddress(&p_hh, g_hh);
    cudaGetSymbolAddress(&p_z, g_z);
    cudaGetSymbolAddress(&p_pre, g_pre);

    const int B = (n + 2047) / 2048;
    const int e4 = e / 4;
    const int rem = e - e4 * 4;
    const int hb = (e4 + 255) / 256;

    // launch 1: zero counts + flags
    k_zero<<<(n + 1023) / 1024, 1024>>>(n);
    // launch 2: histogram (int4) + weight convert
    k_histcvt<<<hb + 192, 256>>>((const int4*)dst, e4, rem, hb, dst,
                                 Wl1, Wr1, Wl2, Wr2);
    // launch 3: scan + fill
    k_scanfill<<<B, 512>>>(n, e);
    // launch 4 (ncu-captured): scatter + x-projection GEMM (A staged once)
    k_scatxproj<<<ntiles + SCAT_BLOCKS, 256, XP_SMEM>>>(
        x, b1, (uint32_t*)p_u, (uint32_t*)p_v, n, src, dst, e, ntiles);
    // launch 5: fused aggregation + relu
    k_aggrelu<<<(n + 7) / 8, 256>>>((const uint4*)p_u, (const uint2*)p_v,
                                    (uint2*)p_hh, n);
    // launch 6: layer-2 projections
    mma_zp<<<ntiles, 256, ZP_SMEM>>>(b2, (uint32_t*)p_z, (uint32_t*)p_pre, n);
    // launch 7: fused aggregation + log_softmax
    k_agg64out<<<(n + 7) / 8, 256>>>((const uint4*)p_z, (const uint4*)p_pre,
                                     (float4*)out, n);
}